// round 10
// baseline (speedup 1.0000x reference)
#include <cuda_runtime.h>
#include <cuda_fp16.h>
#include <cstdint>

// ---------------------------------------------------------------------------
// B=8, L=4096, D=1024, H=8, DH=128, WIN=128; M = 32768.
// GEMMs: mma.sync m16n8k16 fp16 (legacy pipe floor ~340 TF/s), perm64
// operands, 128x128 CTA tiles, 2 CTAs/SM. qkv GEMM epilogue applies rope
// (fp32, via smem bounce). Attention: persistent 148-CTA kernel, double-
// buffered cp.async across tiles, no rope pass, P in registers.
// ---------------------------------------------------------------------------

__device__ float  g_ada [8 * 6144];
__device__ __half g_x1  [33554432];
__device__ __half g_qkv [100663296];
__device__ __half g_o   [33554432];
__device__ float  g_res [33554432];
__device__ __half g_h   [33554432];
__device__ __half g_h1  [134217728];
__device__ float2 g_rope[8192];
__device__ __half g_wqkv[3145728];
__device__ __half g_wout[1048576];
__device__ __half g_wff1[4194304];
__device__ __half g_wff2[4194304];

// ---------------------------------------------------------------------------
// helpers
// ---------------------------------------------------------------------------
__device__ __forceinline__ float gelu_tanh(float x) {
    float u = 0.7978845608028654f * (x + 0.044715f * x * x * x);
    return 0.5f * x * (1.f + tanhf(u));
}

__device__ __forceinline__ uint32_t smem_u32(const void* p) {
    uint32_t a;
    asm("{ .reg .u64 t; cvta.to.shared.u64 t, %1; cvt.u32.u64 %0, t; }" : "=r"(a) : "l"(p));
    return a;
}

__device__ __forceinline__ uint32_t h2u(half2 h) {
    uint32_t u;
    memcpy(&u, &h, 4);
    return u;
}

// perm64 operand layout: applied to BOTH A and B k-dims (dot-product invariant)
__device__ __forceinline__ int perm64h(int k) {
    const int base  = k & ~63;
    const int sb    = (k >> 5) & 1;
    const int b16   = (k >> 4) & 1;
    const int j     = (k & 15) >> 1;
    const int owner = j & 3, hi = j >> 2;
    return base + (owner * 2 + sb) * 8 + b16 * 4 + hi * 2 + (k & 1);
}
__device__ __forceinline__ int perm64c(int col) { return perm64h(col); }

__device__ __forceinline__ void mma16(float* d, uint32_t a0, uint32_t a1,
                                      uint32_t a2, uint32_t a3,
                                      uint32_t b0, uint32_t b1) {
    asm volatile(
        "mma.sync.aligned.m16n8k16.row.col.f32.f16.f16.f32 "
        "{%0,%1,%2,%3}, {%4,%5,%6,%7}, {%8,%9}, {%0,%1,%2,%3};"
        : "+f"(d[0]), "+f"(d[1]), "+f"(d[2]), "+f"(d[3])
        : "r"(a0), "r"(a1), "r"(a2), "r"(a3), "r"(b0), "r"(b1));
}

__device__ __forceinline__ void ldsm_x4(uint32_t& r0, uint32_t& r1,
                                        uint32_t& r2, uint32_t& r3, uint32_t a) {
    asm volatile("ldmatrix.sync.aligned.m8n8.x4.shared.b16 {%0,%1,%2,%3}, [%4];"
                 : "=r"(r0), "=r"(r1), "=r"(r2), "=r"(r3) : "r"(a));
}
__device__ __forceinline__ void ldsm_x4t(uint32_t& r0, uint32_t& r1,
                                         uint32_t& r2, uint32_t& r3, uint32_t a) {
    asm volatile("ldmatrix.sync.aligned.m8n8.x4.trans.shared.b16 {%0,%1,%2,%3}, [%4];"
                 : "=r"(r0), "=r"(r1), "=r"(r2), "=r"(r3) : "r"(a));
}

__device__ __forceinline__ uint4 lds128(uint32_t a) {
    uint4 v;
    asm volatile("ld.shared.v4.u32 {%0,%1,%2,%3}, [%4];"
                 : "=r"(v.x), "=r"(v.y), "=r"(v.z), "=r"(v.w) : "r"(a));
    return v;
}

__device__ __forceinline__ void cp16(uint32_t dst, const void* src) {
    asm volatile("cp.async.cg.shared.global [%0], [%1], 16;" :: "r"(dst), "l"(src));
}
#define CP_COMMIT() asm volatile("cp.async.commit_group;" ::: "memory")
#define CP_WAIT1()  asm volatile("cp.async.wait_group 1;"  ::: "memory")
#define CP_WAIT0()  asm volatile("cp.async.wait_group 0;"  ::: "memory")

// ---------------------------------------------------------------------------
// Kernel 0: Wt[n][perm64(k)] = fp16(W[k][n])
// ---------------------------------------------------------------------------
__global__ void __launch_bounds__(256) transpose_round(
    const float* __restrict__ W, __half* __restrict__ Wt, int K, int N)
{
    __shared__ float t[32][33];
    const int kb = blockIdx.y * 32, nb = blockIdx.x * 32;
    const int tx = threadIdx.x, ty = threadIdx.y;
    #pragma unroll
    for (int i = 0; i < 4; i++)
        t[ty + 8 * i][tx] = W[(size_t)(kb + ty + 8 * i) * N + nb + tx];
    __syncthreads();
    #pragma unroll
    for (int i = 0; i < 4; i++)
        Wt[(size_t)(nb + ty + 8 * i) * K + perm64h(kb + tx)] =
            __float2half_rn(t[tx][ty + 8 * i]);
}

// ---------------------------------------------------------------------------
// Kernel 1: ada = silu(context) @ W_ada + b_ada
// ---------------------------------------------------------------------------
__global__ void __launch_bounds__(256) ada_kernel(
    const float* __restrict__ ctx, const float* __restrict__ W,
    const float* __restrict__ bias, float* __restrict__ ada)
{
    __shared__ float sctx[8 * 1024];
    for (int i = threadIdx.x; i < 8192; i += 256) {
        float c = ctx[i];
        sctx[i] = c / (1.f + __expf(-c));
    }
    __syncthreads();
    const int col = blockIdx.x * 256 + threadIdx.x;
    float acc[8] = {0, 0, 0, 0, 0, 0, 0, 0};
    for (int k = 0; k < 1024; k++) {
        float w = W[(size_t)k * 6144 + col];
        #pragma unroll
        for (int b = 0; b < 8; b++) acc[b] += sctx[b * 1024 + k] * w;
    }
    float bv = bias[col];
    #pragma unroll
    for (int b = 0; b < 8; b++) ada[b * 6144 + col] = acc[b] + bv;
}

// ---------------------------------------------------------------------------
// Kernel 2: rope table (sin, cos)
// ---------------------------------------------------------------------------
__global__ void rope_kernel(float2* __restrict__ tab)
{
    int idx = blockIdx.x * 256 + threadIdx.x;
    if (idx < 8192) {
        int pos = idx >> 6;
        int i   = idx & 63;
        float freq = powf(10000.f, -(float)(2 * i) / 128.f);
        float ang  = (float)pos * freq;
        tab[idx] = make_float2(sinf(ang), cosf(ang));
    }
}

// ---------------------------------------------------------------------------
// Kernel 3: rmsnorm + modulate -> fp16 perm64
// ---------------------------------------------------------------------------
__global__ void __launch_bounds__(256) norm_mod(
    const float* __restrict__ x, const float* __restrict__ scale,
    const float* __restrict__ ada, int shOff, int scOff,
    __half* __restrict__ y)
{
    const int row = blockIdx.x;
    const int b   = row >> 12;
    const float4 v = ((const float4*)(x + (size_t)row * 1024))[threadIdx.x];

    float ss = v.x * v.x + v.y * v.y + v.z * v.z + v.w * v.w;
    #pragma unroll
    for (int o = 16; o > 0; o >>= 1) ss += __shfl_xor_sync(0xffffffffu, ss, o);
    __shared__ float ws[8];
    if ((threadIdx.x & 31) == 0) ws[threadIdx.x >> 5] = ss;
    __syncthreads();
    float tot = 0.f;
    #pragma unroll
    for (int i = 0; i < 8; i++) tot += ws[i];
    const float r = rsqrtf(tot * (1.f / 1024.f) + 1e-5f);

    const int c = threadIdx.x * 4;
    const float* ab = ada + b * 6144;
    const float4 s   = *(const float4*)(scale + c);
    const float4 sh  = *(const float4*)(ab + shOff + c);
    const float4 scm = *(const float4*)(ab + scOff + c);
    float o0 = v.x * r * s.x * (1.f + scm.x) + sh.x;
    float o1 = v.y * r * s.y * (1.f + scm.y) + sh.y;
    float o2 = v.z * r * s.z * (1.f + scm.z) + sh.z;
    float o3 = v.w * r * s.w * (1.f + scm.w) + sh.w;
    __half* yr = y + (size_t)row * 1024;
    *(half2*)(yr + perm64c(c))     = __floats2half2_rn(o0, o1);
    *(half2*)(yr + perm64c(c + 2)) = __floats2half2_rn(o2, o3);
}

// ---------------------------------------------------------------------------
// Kernel 4: fp16 GEMM, C[M,N] = A[M,K] @ Bt[N,K]^T  (+epilogue)
//   CTA 128x128, BK=64, 8 warps (4x2) of 32x64. 2 CTAs/SM.
//   MODE 0: fp32. 1: fp16-perm64 gelu. 2: fp32 res+gate*C.
//   MODE 3: fp16 natural store with fused rope for q/k column blocks.
// ---------------------------------------------------------------------------
#define STAGE_BYTES 32768
#define GEMM_SMEM   66560    // max(2*32768, 128*130*4 fp32 rope scratch)

template <int MODE>
__global__ void __launch_bounds__(256, 2) gemm_fp16(
    const __half* __restrict__ A, const __half* __restrict__ Bt,
    const float* __restrict__ bias,
    float* __restrict__ C, __half* __restrict__ Ch,
    int N, int K,
    const float* __restrict__ res, const float* __restrict__ gate,
    const float2* __restrict__ rope)
{
    extern __shared__ char smem[];
    const uint32_t sm_u = smem_u32(smem);

    const int tid  = threadIdx.x;
    const int lane = tid & 31;
    const int warp = tid >> 5;
    const int g    = lane >> 2, tig = lane & 3;
    const int wm   = warp & 3;
    const int wn   = warp >> 2;
    const int cm   = blockIdx.y << 7;
    const int cn   = blockIdx.x << 7;
    const int KT   = K >> 6;

    const int f_row = tid >> 3;
    const int f_ch  = tid & 7;

    auto fill = [&](int kt, int s) {
        const uint32_t sb_ = sm_u + s * STAGE_BYTES;
        const __half* Ag = A + (size_t)(cm + f_row) * K + (kt << 6) + f_ch * 8;
        #pragma unroll
        for (int i = 0; i < 4; i++) {
            const int row = f_row + i * 32;
            cp16(sb_ + row * 128 + ((f_ch ^ (row & 7)) << 4),
                 Ag + (size_t)i * 32 * K);
        }
        const __half* Bg = Bt + (size_t)(cn + f_row) * K + (kt << 6) + f_ch * 8;
        #pragma unroll
        for (int i = 0; i < 4; i++) {
            const int row = f_row + i * 32;
            cp16(sb_ + 16384 + row * 128 + ((f_ch ^ (row & 7)) << 4),
                 Bg + (size_t)i * 32 * K);
        }
    };

    float acc[2][8][4];
    #pragma unroll
    for (int mt = 0; mt < 2; mt++)
        #pragma unroll
        for (int nt = 0; nt < 8; nt++)
            #pragma unroll
            for (int i = 0; i < 4; i++) acc[mt][nt][i] = 0.f;

    fill(0, 0); CP_COMMIT();

    for (int kt = 0; kt < KT; kt++) {
        const int buf = kt & 1;
        if (kt + 1 < KT) { fill(kt + 1, buf ^ 1); CP_COMMIT(); CP_WAIT1(); }
        else             { CP_WAIT0(); }
        __syncthreads();

        const uint32_t a_base = sm_u + buf * STAGE_BYTES;
        const uint32_t b_base = a_base + 16384;
        #pragma unroll
        for (int sb = 0; sb < 2; sb++) {
            const int chn = (tig << 1) | sb;
            uint4 al[2], ah[2];
            #pragma unroll
            for (int mt = 0; mt < 2; mt++) {
                const int rl = wm * 32 + mt * 16 + g;
                al[mt] = lds128(a_base + rl * 128 + ((chn ^ (rl & 7)) << 4));
                ah[mt] = lds128(a_base + (rl + 8) * 128 + ((chn ^ (rl & 7)) << 4));
            }
            #pragma unroll
            for (int nt = 0; nt < 8; nt++) {
                const int rb = wn * 64 + nt * 8 + g;
                const uint4 bb = lds128(b_base + rb * 128 + ((chn ^ (rb & 7)) << 4));
                #pragma unroll
                for (int mt = 0; mt < 2; mt++) {
                    mma16(acc[mt][nt], al[mt].x, ah[mt].x, al[mt].y, ah[mt].y,
                          bb.x, bb.y);
                    mma16(acc[mt][nt], al[mt].z, ah[mt].z, al[mt].w, ah[mt].w,
                          bb.z, bb.w);
                }
            }
        }
        __syncthreads();
    }

    if (MODE == 3 && cn < 2048) {
        // ---- fused rope path (q and k column blocks) ----
        float* sc = (float*)smem;   // [128][130]
        #pragma unroll
        for (int mt = 0; mt < 2; mt++) {
            const int r0 = wm * 32 + mt * 16 + g;
            #pragma unroll
            for (int nt = 0; nt < 8; nt++) {
                const int c = wn * 64 + nt * 8 + (tig << 1);
                const float bi0 = bias[cn + c], bi1 = bias[cn + c + 1];
                sc[r0 * 130 + c]           = acc[mt][nt][0] + bi0;
                sc[r0 * 130 + c + 1]       = acc[mt][nt][1] + bi1;
                sc[(r0 + 8) * 130 + c]     = acc[mt][nt][2] + bi0;
                sc[(r0 + 8) * 130 + c + 1] = acc[mt][nt][3] + bi1;
            }
        }
        __syncthreads();
        const int r  = tid >> 1;          // row 0..127 (== window position)
        const int hh = tid & 1;           // 0: cols 0..63, 1: cols 64..127
        const float* srow = sc + r * 130 + hh * 64;
        const float* prow = sc + r * 130 + (hh ^ 1) * 64;
        __half* drow = Ch + (size_t)(cm + r) * N + cn + hh * 64;
        const float2* rt = rope + r * 64 + hh * 32;
        #pragma unroll
        for (int jj = 0; jj < 32; jj++) {
            const float2 t = rt[jj];
            const float ax = srow[2 * jj], ay = srow[2 * jj + 1];
            const float bx = prow[2 * jj], by = prow[2 * jj + 1];
            float o0, o1;
            if (hh == 0) { o0 = ax * t.y - bx * t.x; o1 = ay * t.y - by * t.x; }
            else         { o0 = ax * t.y + bx * t.x; o1 = ay * t.y + by * t.x; }
            *(half2*)(drow + 2 * jj) = __floats2half2_rn(o0, o1);
        }
        return;
    }

    const int bb_i = cm >> 12;
    #pragma unroll
    for (int mt = 0; mt < 2; mt++) {
        const int row0 = cm + wm * 32 + mt * 16 + g;
        #pragma unroll
        for (int nt = 0; nt < 8; nt++) {
            const int col = cn + wn * 64 + nt * 8 + (tig << 1);
            const float bi0 = bias[col], bi1 = bias[col + 1];
            float v0 = acc[mt][nt][0] + bi0;
            float v1 = acc[mt][nt][1] + bi1;
            float v2 = acc[mt][nt][2] + bi0;
            float v3 = acc[mt][nt][3] + bi1;
            if (MODE == 1) {
                v0 = gelu_tanh(v0); v1 = gelu_tanh(v1);
                v2 = gelu_tanh(v2); v3 = gelu_tanh(v3);
                const int p = perm64c(col);
                *(half2*)(Ch + (size_t)row0 * N + p)       = __floats2half2_rn(v0, v1);
                *(half2*)(Ch + (size_t)(row0 + 8) * N + p) = __floats2half2_rn(v2, v3);
            } else if (MODE == 3) {
                *(half2*)(Ch + (size_t)row0 * N + col)       = __floats2half2_rn(v0, v1);
                *(half2*)(Ch + (size_t)(row0 + 8) * N + col) = __floats2half2_rn(v2, v3);
            } else {
                if (MODE == 2) {
                    const float g0 = gate[bb_i * 6144 + col];
                    const float g1 = gate[bb_i * 6144 + col + 1];
                    const float2 r0 = *(const float2*)(res + (size_t)row0 * N + col);
                    const float2 r1 = *(const float2*)(res + (size_t)(row0 + 8) * N + col);
                    v0 = r0.x + g0 * v0;  v1 = r0.y + g1 * v1;
                    v2 = r1.x + g0 * v2;  v3 = r1.y + g1 * v3;
                }
                *(float2*)(C + (size_t)row0 * N + col)       = make_float2(v0, v1);
                *(float2*)(C + (size_t)(row0 + 8) * N + col) = make_float2(v2, v3);
            }
        }
    }
}

// ---------------------------------------------------------------------------
// Kernel 5: persistent windowed attention (rope pre-applied in qkv).
//   148 CTAs, grid-stride over 2048 (window,head) tiles, double-buffered
//   cp.async prefetch of the next tile, 256B swizzled rows.
// ---------------------------------------------------------------------------
#define AT_BUF  98304
#define ATTN_SMEM_BYTES (2 * AT_BUF)
#define AT_NTILES 2048
#define AT_GRID   148

__global__ void __launch_bounds__(256) attn_kernel(
    const __half* __restrict__ qkv, __half* __restrict__ obuf)
{
    extern __shared__ char sha[];
    const uint32_t sm_u = smem_u32(sha);

    const int tid  = threadIdx.x;
    const int lane = tid & 31, warp = tid >> 5;
    const int tig  = lane & 3;

    const int s_row = tid >> 4, s_ch = tid & 15;

    auto stage = [&](int tile, int buf) {
        const int w = tile >> 3, h = tile & 7;
        const size_t rb = (size_t)w * 128;
        const uint32_t q_u = sm_u + buf * AT_BUF;
        const __half* base = qkv + (rb + s_row) * 3072 + h * 128 + s_ch * 8;
        #pragma unroll
        for (int i = 0; i < 8; i++) {
            const int r = s_row + i * 16;
            const uint32_t off = r * 256 + ((s_ch ^ (r & 7)) << 4);
            const __half* src = base + (size_t)i * 16 * 3072;
            cp16(q_u + off,         src);
            cp16(q_u + 32768 + off, src + 1024);
            cp16(q_u + 65536 + off, src + 2048);
        }
    };

    const int first = blockIdx.x;
    if (first < AT_NTILES) { stage(first, 0); }
    CP_COMMIT();

    const int m0 = warp * 16;
    const int l7 = lane & 7;
    const int a_row = m0 + l7 + ((lane & 8) ? 8 : 0);
    const int a_kc8 = (lane & 16) ? 1 : 0;
    const int b_row = l7 + ((lane & 16) ? 8 : 0);
    const int b_kc8 = (lane & 8) ? 1 : 0;
    const int v_row = l7 + ((lane & 8) ? 8 : 0);
    const int v_dc8 = (lane & 16) ? 1 : 0;

    int buf = 0;
    for (int tile = first, idx = 0; tile < AT_NTILES; tile += AT_GRID, idx++) {
        if (idx > 0) __syncthreads();          // done reading buf before restage
        if (tile + AT_GRID < AT_NTILES) stage(tile + AT_GRID, buf ^ 1);
        CP_COMMIT();
        CP_WAIT1();
        __syncthreads();

        const uint32_t q_u = sm_u + buf * AT_BUF;
        const uint32_t k_u = q_u + 32768;
        const uint32_t v_u = q_u + 65536;
        const int h = tile & 7;
        const size_t rowbase = (size_t)(tile >> 3) * 128;

        // ---- scores: S = Q K^T ----
        float acc[16][4];
        #pragma unroll
        for (int nt = 0; nt < 16; nt++)
            #pragma unroll
            for (int i = 0; i < 4; i++) acc[nt][i] = 0.f;

        #pragma unroll
        for (int kc = 0; kc < 8; kc++) {
            uint32_t a0, a1, a2, a3;
            const int ca = (kc * 2 + a_kc8) ^ (a_row & 7);
            ldsm_x4(a0, a1, a2, a3, q_u + a_row * 256 + (ca << 4));
            #pragma unroll
            for (int np = 0; np < 8; np++) {
                const int row = np * 16 + b_row;
                const int cb = (kc * 2 + b_kc8) ^ (row & 7);
                uint32_t b0, b1, c0, c1;
                ldsm_x4(b0, b1, c0, c1, k_u + row * 256 + (cb << 4));
                mma16(acc[2 * np],     a0, a1, a2, a3, b0, b1);
                mma16(acc[2 * np + 1], a0, a1, a2, a3, c0, c1);
            }
        }

        // ---- softmax ----
        const float scl = 0.08838834764831845f;
        float mx0 = -1e30f, mx1 = -1e30f;
        #pragma unroll
        for (int nt = 0; nt < 16; nt++) {
            acc[nt][0] *= scl; acc[nt][1] *= scl;
            acc[nt][2] *= scl; acc[nt][3] *= scl;
            mx0 = fmaxf(mx0, fmaxf(acc[nt][0], acc[nt][1]));
            mx1 = fmaxf(mx1, fmaxf(acc[nt][2], acc[nt][3]));
        }
        mx0 = fmaxf(mx0, __shfl_xor_sync(0xffffffffu, mx0, 1));
        mx0 = fmaxf(mx0, __shfl_xor_sync(0xffffffffu, mx0, 2));
        mx1 = fmaxf(mx1, __shfl_xor_sync(0xffffffffu, mx1, 1));
        mx1 = fmaxf(mx1, __shfl_xor_sync(0xffffffffu, mx1, 2));

        float s0 = 0.f, s1 = 0.f;
        #pragma unroll
        for (int nt = 0; nt < 16; nt++) {
            acc[nt][0] = __expf(acc[nt][0] - mx0);
            acc[nt][1] = __expf(acc[nt][1] - mx0);
            acc[nt][2] = __expf(acc[nt][2] - mx1);
            acc[nt][3] = __expf(acc[nt][3] - mx1);
            s0 += acc[nt][0] + acc[nt][1];
            s1 += acc[nt][2] + acc[nt][3];
        }
        s0 += __shfl_xor_sync(0xffffffffu, s0, 1);
        s0 += __shfl_xor_sync(0xffffffffu, s0, 2);
        s1 += __shfl_xor_sync(0xffffffffu, s1, 1);
        s1 += __shfl_xor_sync(0xffffffffu, s1, 2);
        const float i0 = 1.f / s0, i1 = 1.f / s1;

        // ---- O = P V ----
        float o[16][4];
        #pragma unroll
        for (int nt = 0; nt < 16; nt++)
            #pragma unroll
            for (int i = 0; i < 4; i++) o[nt][i] = 0.f;

        #pragma unroll
        for (int kc = 0; kc < 8; kc++) {
            const uint32_t a0 = h2u(__floats2half2_rn(acc[2 * kc][0] * i0, acc[2 * kc][1] * i0));
            const uint32_t a1 = h2u(__floats2half2_rn(acc[2 * kc][2] * i1, acc[2 * kc][3] * i1));
            const uint32_t a2 = h2u(__floats2half2_rn(acc[2 * kc + 1][0] * i0, acc[2 * kc + 1][1] * i0));
            const uint32_t a3 = h2u(__floats2half2_rn(acc[2 * kc + 1][2] * i1, acc[2 * kc + 1][3] * i1));
            #pragma unroll
            for (int dp = 0; dp < 8; dp++) {
                const int row = kc * 16 + v_row;
                const int cv = (dp * 2 + v_dc8) ^ (row & 7);
                uint32_t b0, b1, c0, c1;
                ldsm_x4t(b0, b1, c0, c1, v_u + row * 256 + (cv << 4));
                mma16(o[2 * dp],     a0, a1, a2, a3, b0, b1);
                mma16(o[2 * dp + 1], a0, a1, a2, a3, c0, c1);
            }
        }

        // ---- store O as fp16 perm64 ----
        const int gq = lane >> 2;
        #pragma unroll
        for (int nt = 0; nt < 16; nt++) {
            const int col = h * 128 + nt * 8 + (tig << 1);
            const int p = perm64c(col);
            *(half2*)(obuf + (rowbase + m0 + gq) * 1024 + p) =
                __floats2half2_rn(o[nt][0], o[nt][1]);
            *(half2*)(obuf + (rowbase + m0 + gq + 8) * 1024 + p) =
                __floats2half2_rn(o[nt][2], o[nt][3]);
        }
        buf ^= 1;
    }
}

// ---------------------------------------------------------------------------
// host launcher
// ---------------------------------------------------------------------------
extern "C" void kernel_launch(void* const* d_in, const int* in_sizes, int n_in,
                              void* d_out, int out_size)
{
    const float* group_x = (const float*)d_in[0];
    const float* context = (const float*)d_in[1];
    const float* W_ada   = (const float*)d_in[2];
    const float* b_ada   = (const float*)d_in[3];
    const float* scale1  = (const float*)d_in[4];
    const float* W_qkv   = (const float*)d_in[5];
    const float* b_qkv   = (const float*)d_in[6];
    const float* W_out   = (const float*)d_in[7];
    const float* b_out   = (const float*)d_in[8];
    const float* scale2  = (const float*)d_in[9];
    const float* W_ff1   = (const float*)d_in[10];
    const float* b_ff1   = (const float*)d_in[11];
    const float* W_ff2   = (const float*)d_in[12];
    const float* b_ff2   = (const float*)d_in[13];
    float* out = (float*)d_out;

    float *ada, *res2;
    __half *x1, *qkv, *obuf, *hbuf, *h1, *wqkv, *wout, *wff1, *wff2;
    float2* rope;
    cudaGetSymbolAddress((void**)&ada,  g_ada);
    cudaGetSymbolAddress((void**)&x1,   g_x1);
    cudaGetSymbolAddress((void**)&qkv,  g_qkv);
    cudaGetSymbolAddress((void**)&obuf, g_o);
    cudaGetSymbolAddress((void**)&res2, g_res);
    cudaGetSymbolAddress((void**)&hbuf, g_h);
    cudaGetSymbolAddress((void**)&h1,   g_h1);
    cudaGetSymbolAddress((void**)&rope, g_rope);
    cudaGetSymbolAddress((void**)&wqkv, g_wqkv);
    cudaGetSymbolAddress((void**)&wout, g_wout);
    cudaGetSymbolAddress((void**)&wff1, g_wff1);
    cudaGetSymbolAddress((void**)&wff2, g_wff2);

    cudaFuncSetAttribute(gemm_fp16<1>, cudaFuncAttributeMaxDynamicSharedMemorySize, GEMM_SMEM);
    cudaFuncSetAttribute(gemm_fp16<2>, cudaFuncAttributeMaxDynamicSharedMemorySize, GEMM_SMEM);
    cudaFuncSetAttribute(gemm_fp16<3>, cudaFuncAttributeMaxDynamicSharedMemorySize, GEMM_SMEM);
    cudaFuncSetAttribute(attn_kernel,  cudaFuncAttributeMaxDynamicSharedMemorySize, ATTN_SMEM_BYTES);

    const dim3 tb(32, 8);
    // order chosen so launch #6 (ncu -s 5 -c 1) is the qkv GEMM
    ada_kernel<<<24, 256>>>(context, W_ada, b_ada, ada);                        // 1
    rope_kernel<<<32, 256>>>(rope);                                             // 2
    norm_mod<<<32768, 256>>>(group_x, scale1, ada, 0, 1024, x1);                // 3
    transpose_round<<<dim3(3072 / 32, 1024 / 32), tb>>>(W_qkv, wqkv, 1024, 3072); // 4
    transpose_round<<<dim3(1024 / 32, 1024 / 32), tb>>>(W_out, wout, 1024, 1024); // 5

    // 6: qkv = x1 @ W_qkv + b_qkv -> fp16 natural, rope fused (N=3072, K=1024)
    gemm_fp16<3><<<dim3(24, 256), 256, GEMM_SMEM>>>(x1, wqkv, b_qkv, nullptr, qkv,
                                                    3072, 1024, nullptr, nullptr, rope);

    transpose_round<<<dim3(4096 / 32, 1024 / 32), tb>>>(W_ff1, wff1, 1024, 4096); // 7
    transpose_round<<<dim3(1024 / 32, 4096 / 32), tb>>>(W_ff2, wff2, 4096, 1024); // 8

    attn_kernel<<<AT_GRID, 256, ATTN_SMEM_BYTES>>>(qkv, obuf);                  // 9

    // res2 = group_x + g_msa * (obuf @ W_out + b_out)   (N=1024, K=1024)
    gemm_fp16<2><<<dim3(8, 256), 256, GEMM_SMEM>>>(obuf, wout, b_out, res2, nullptr,
                                                   1024, 1024, group_x, ada + 2048, nullptr);
    norm_mod<<<32768, 256>>>(res2, scale2, ada, 3072, 4096, hbuf);

    // h1 = gelu(hbuf @ W_ff1 + b_ff1) -> fp16 perm64  (N=4096, K=1024)
    gemm_fp16<1><<<dim3(32, 256), 256, GEMM_SMEM>>>(hbuf, wff1, b_ff1, nullptr, h1,
                                                    4096, 1024, nullptr, nullptr, nullptr);
    // out = res2 + g_mlp * (h1 @ W_ff2 + b_ff2)        (N=1024, K=4096)
    gemm_fp16<2><<<dim3(8, 256), 256, GEMM_SMEM>>>(h1, wff2, b_ff2, out, nullptr,
                                                   1024, 4096, res2, ada + 5120, nullptr);
}

// round 11
// speedup vs baseline: 1.0821x; 1.0821x over previous
#include <cuda_runtime.h>
#include <cuda_fp16.h>
#include <cstdint>

// ---------------------------------------------------------------------------
// B=8, L=4096, D=1024, H=8, DH=128, WIN=128; M = 32768.
// GEMMs: R7 config (best measured): mma.sync m16n8k16 fp16, perm64 operands,
// CTA 128x256, 8 warps of 64x64, 3-stage cp.async.
// Attention: 2 CTAs/SM, single-buffered tiles; cross-CTA latency hiding.
// ---------------------------------------------------------------------------

__device__ float  g_ada [8 * 6144];
__device__ __half g_x1  [33554432];
__device__ __half g_qkv [100663296];
__device__ __half g_o   [33554432];
__device__ float  g_res [33554432];
__device__ __half g_h   [33554432];
__device__ __half g_h1  [134217728];
__device__ float2 g_rope[8192];
__device__ __half g_wqkv[3145728];
__device__ __half g_wout[1048576];
__device__ __half g_wff1[4194304];
__device__ __half g_wff2[4194304];

// ---------------------------------------------------------------------------
// helpers
// ---------------------------------------------------------------------------
__device__ __forceinline__ float gelu_tanh(float x) {
    float u = 0.7978845608028654f * (x + 0.044715f * x * x * x);
    return 0.5f * x * (1.f + tanhf(u));
}

__device__ __forceinline__ uint32_t smem_u32(const void* p) {
    uint32_t a;
    asm("{ .reg .u64 t; cvta.to.shared.u64 t, %1; cvt.u32.u64 %0, t; }" : "=r"(a) : "l"(p));
    return a;
}

__device__ __forceinline__ uint32_t h2u(half2 h) {
    uint32_t u;
    memcpy(&u, &h, 4);
    return u;
}

// perm64 operand layout: applied to BOTH A and B k-dims (dot-product invariant)
__device__ __forceinline__ int perm64h(int k) {
    const int base  = k & ~63;
    const int sb    = (k >> 5) & 1;
    const int b16   = (k >> 4) & 1;
    const int j     = (k & 15) >> 1;
    const int owner = j & 3, hi = j >> 2;
    return base + (owner * 2 + sb) * 8 + b16 * 4 + hi * 2 + (k & 1);
}
__device__ __forceinline__ int perm64c(int col) { return perm64h(col); }

__device__ __forceinline__ void mma16(float* d, uint32_t a0, uint32_t a1,
                                      uint32_t a2, uint32_t a3,
                                      uint32_t b0, uint32_t b1) {
    asm volatile(
        "mma.sync.aligned.m16n8k16.row.col.f32.f16.f16.f32 "
        "{%0,%1,%2,%3}, {%4,%5,%6,%7}, {%8,%9}, {%0,%1,%2,%3};"
        : "+f"(d[0]), "+f"(d[1]), "+f"(d[2]), "+f"(d[3])
        : "r"(a0), "r"(a1), "r"(a2), "r"(a3), "r"(b0), "r"(b1));
}

__device__ __forceinline__ void ldsm_x4(uint32_t& r0, uint32_t& r1,
                                        uint32_t& r2, uint32_t& r3, uint32_t a) {
    asm volatile("ldmatrix.sync.aligned.m8n8.x4.shared.b16 {%0,%1,%2,%3}, [%4];"
                 : "=r"(r0), "=r"(r1), "=r"(r2), "=r"(r3) : "r"(a));
}
__device__ __forceinline__ void ldsm_x4t(uint32_t& r0, uint32_t& r1,
                                         uint32_t& r2, uint32_t& r3, uint32_t a) {
    asm volatile("ldmatrix.sync.aligned.m8n8.x4.trans.shared.b16 {%0,%1,%2,%3}, [%4];"
                 : "=r"(r0), "=r"(r1), "=r"(r2), "=r"(r3) : "r"(a));
}

__device__ __forceinline__ uint4 lds128(uint32_t a) {
    uint4 v;
    asm volatile("ld.shared.v4.u32 {%0,%1,%2,%3}, [%4];"
                 : "=r"(v.x), "=r"(v.y), "=r"(v.z), "=r"(v.w) : "r"(a));
    return v;
}

__device__ __forceinline__ void cp16(uint32_t dst, const void* src) {
    asm volatile("cp.async.cg.shared.global [%0], [%1], 16;" :: "r"(dst), "l"(src));
}
#define CP_COMMIT() asm volatile("cp.async.commit_group;" ::: "memory")
#define CP_WAIT1()  asm volatile("cp.async.wait_group 1;"  ::: "memory")
#define CP_WAIT0()  asm volatile("cp.async.wait_group 0;"  ::: "memory")

// ---------------------------------------------------------------------------
// Kernel 0: Wt[n][perm64(k)] = fp16(W[k][n])
// ---------------------------------------------------------------------------
__global__ void __launch_bounds__(256) transpose_round(
    const float* __restrict__ W, __half* __restrict__ Wt, int K, int N)
{
    __shared__ float t[32][33];
    const int kb = blockIdx.y * 32, nb = blockIdx.x * 32;
    const int tx = threadIdx.x, ty = threadIdx.y;
    #pragma unroll
    for (int i = 0; i < 4; i++)
        t[ty + 8 * i][tx] = W[(size_t)(kb + ty + 8 * i) * N + nb + tx];
    __syncthreads();
    #pragma unroll
    for (int i = 0; i < 4; i++)
        Wt[(size_t)(nb + ty + 8 * i) * K + perm64h(kb + tx)] =
            __float2half_rn(t[tx][ty + 8 * i]);
}

// ---------------------------------------------------------------------------
// Kernel 1: ada = silu(context) @ W_ada + b_ada
// ---------------------------------------------------------------------------
__global__ void __launch_bounds__(256) ada_kernel(
    const float* __restrict__ ctx, const float* __restrict__ W,
    const float* __restrict__ bias, float* __restrict__ ada)
{
    __shared__ float sctx[8 * 1024];
    for (int i = threadIdx.x; i < 8192; i += 256) {
        float c = ctx[i];
        sctx[i] = c / (1.f + __expf(-c));
    }
    __syncthreads();
    const int col = blockIdx.x * 256 + threadIdx.x;
    float acc[8] = {0, 0, 0, 0, 0, 0, 0, 0};
    for (int k = 0; k < 1024; k++) {
        float w = W[(size_t)k * 6144 + col];
        #pragma unroll
        for (int b = 0; b < 8; b++) acc[b] += sctx[b * 1024 + k] * w;
    }
    float bv = bias[col];
    #pragma unroll
    for (int b = 0; b < 8; b++) ada[b * 6144 + col] = acc[b] + bv;
}

// ---------------------------------------------------------------------------
// Kernel 2: rope table
// ---------------------------------------------------------------------------
__global__ void rope_kernel(float2* __restrict__ tab)
{
    int idx = blockIdx.x * 256 + threadIdx.x;
    if (idx < 8192) {
        int pos = idx >> 6;
        int i   = idx & 63;
        float freq = powf(10000.f, -(float)(2 * i) / 128.f);
        float ang  = (float)pos * freq;
        tab[idx] = make_float2(sinf(ang), cosf(ang));
    }
}

// ---------------------------------------------------------------------------
// Kernel 3: rmsnorm + modulate -> fp16 perm64
// ---------------------------------------------------------------------------
__global__ void __launch_bounds__(256) norm_mod(
    const float* __restrict__ x, const float* __restrict__ scale,
    const float* __restrict__ ada, int shOff, int scOff,
    __half* __restrict__ y)
{
    const int row = blockIdx.x;
    const int b   = row >> 12;
    const float4 v = ((const float4*)(x + (size_t)row * 1024))[threadIdx.x];

    float ss = v.x * v.x + v.y * v.y + v.z * v.z + v.w * v.w;
    #pragma unroll
    for (int o = 16; o > 0; o >>= 1) ss += __shfl_xor_sync(0xffffffffu, ss, o);
    __shared__ float ws[8];
    if ((threadIdx.x & 31) == 0) ws[threadIdx.x >> 5] = ss;
    __syncthreads();
    float tot = 0.f;
    #pragma unroll
    for (int i = 0; i < 8; i++) tot += ws[i];
    const float r = rsqrtf(tot * (1.f / 1024.f) + 1e-5f);

    const int c = threadIdx.x * 4;
    const float* ab = ada + b * 6144;
    const float4 s   = *(const float4*)(scale + c);
    const float4 sh  = *(const float4*)(ab + shOff + c);
    const float4 scm = *(const float4*)(ab + scOff + c);
    float o0 = v.x * r * s.x * (1.f + scm.x) + sh.x;
    float o1 = v.y * r * s.y * (1.f + scm.y) + sh.y;
    float o2 = v.z * r * s.z * (1.f + scm.z) + sh.z;
    float o3 = v.w * r * s.w * (1.f + scm.w) + sh.w;
    __half* yr = y + (size_t)row * 1024;
    *(half2*)(yr + perm64c(c))     = __floats2half2_rn(o0, o1);
    *(half2*)(yr + perm64c(c + 2)) = __floats2half2_rn(o2, o3);
}

// ---------------------------------------------------------------------------
// Kernel 4: fp16 GEMM (R7 config), C[M,N] = A[M,K] @ Bt[N,K]^T  (+epilogue)
//   CTA 128x256, BK=64, 8 warps (2 row x 4 col) of 64x64. 3-stage cp.async.
//   MODE 0: fp32. 1: fp16-perm64 gelu. 2: fp32 res+gate*C. 3: fp16 natural.
// ---------------------------------------------------------------------------
#define STAGE_BYTES 49152            // A: 128*128 + B: 256*128
#define GEMM_SMEM  (3 * STAGE_BYTES)

template <int MODE>
__global__ void __launch_bounds__(256, 1) gemm_fp16(
    const __half* __restrict__ A, const __half* __restrict__ Bt,
    const float* __restrict__ bias,
    float* __restrict__ C, __half* __restrict__ Ch,
    int N, int K,
    const float* __restrict__ res, const float* __restrict__ gate)
{
    extern __shared__ char smem[];
    const uint32_t sm_u = smem_u32(smem);

    const int tid  = threadIdx.x;
    const int lane = tid & 31;
    const int warp = tid >> 5;
    const int g    = lane >> 2, tig = lane & 3;
    const int wm   = warp & 1;
    const int wn   = warp >> 1;
    const int cm   = blockIdx.y << 7;
    const int cn   = blockIdx.x << 8;
    const int KT   = K >> 6;

    const int f_row = tid >> 3;
    const int f_ch  = tid & 7;

    auto fill = [&](int kt, int s) {
        const uint32_t sb_ = sm_u + s * STAGE_BYTES;
        const __half* Ag = A + (size_t)(cm + f_row) * K + (kt << 6) + f_ch * 8;
        #pragma unroll
        for (int i = 0; i < 4; i++) {
            const int row = f_row + i * 32;
            cp16(sb_ + row * 128 + ((f_ch ^ (row & 7)) << 4),
                 Ag + (size_t)i * 32 * K);
        }
        const __half* Bg = Bt + (size_t)(cn + f_row) * K + (kt << 6) + f_ch * 8;
        #pragma unroll
        for (int i = 0; i < 8; i++) {
            const int row = f_row + i * 32;
            cp16(sb_ + 16384 + row * 128 + ((f_ch ^ (row & 7)) << 4),
                 Bg + (size_t)i * 32 * K);
        }
    };

    float acc[4][8][4];
    #pragma unroll
    for (int mt = 0; mt < 4; mt++)
        #pragma unroll
        for (int nt = 0; nt < 8; nt++)
            #pragma unroll
            for (int i = 0; i < 4; i++) acc[mt][nt][i] = 0.f;

    fill(0, 0); CP_COMMIT();
    if (KT > 1) fill(1, 1);
    CP_COMMIT();

    int s = 0;
    for (int kt = 0; kt < KT; kt++) {
        CP_WAIT1();
        __syncthreads();

        const uint32_t a_base = sm_u + s * STAGE_BYTES;
        const uint32_t b_base = a_base + 16384;
        #pragma unroll
        for (int sb = 0; sb < 2; sb++) {
            const int chn = (tig << 1) | sb;
            uint4 al[4], ah[4];
            #pragma unroll
            for (int mt = 0; mt < 4; mt++) {
                const int rl = wm * 64 + mt * 16 + g;
                al[mt] = lds128(a_base + rl * 128 + ((chn ^ (rl & 7)) << 4));
                ah[mt] = lds128(a_base + (rl + 8) * 128 + ((chn ^ (rl & 7)) << 4));
            }
            #pragma unroll
            for (int nt = 0; nt < 8; nt++) {
                const int rb = wn * 64 + nt * 8 + g;
                const uint4 bb = lds128(b_base + rb * 128 + ((chn ^ (rb & 7)) << 4));
                #pragma unroll
                for (int mt = 0; mt < 4; mt++) {
                    mma16(acc[mt][nt], al[mt].x, ah[mt].x, al[mt].y, ah[mt].y,
                          bb.x, bb.y);
                    mma16(acc[mt][nt], al[mt].z, ah[mt].z, al[mt].w, ah[mt].w,
                          bb.z, bb.w);
                }
            }
        }
        if (kt + 2 < KT) fill(kt + 2, (s + 2 >= 3) ? s - 1 : s + 2);
        CP_COMMIT();
        s = (s + 1 == 3) ? 0 : s + 1;
    }

    const int bb_i = cm >> 12;
    #pragma unroll
    for (int mt = 0; mt < 4; mt++) {
        const int row0 = cm + wm * 64 + mt * 16 + g;
        #pragma unroll
        for (int nt = 0; nt < 8; nt++) {
            const int col = cn + wn * 64 + nt * 8 + (tig << 1);
            const float bi0 = bias[col], bi1 = bias[col + 1];
            float v0 = acc[mt][nt][0] + bi0;
            float v1 = acc[mt][nt][1] + bi1;
            float v2 = acc[mt][nt][2] + bi0;
            float v3 = acc[mt][nt][3] + bi1;
            if (MODE == 1) {
                v0 = gelu_tanh(v0); v1 = gelu_tanh(v1);
                v2 = gelu_tanh(v2); v3 = gelu_tanh(v3);
                const int p = perm64c(col);
                *(half2*)(Ch + (size_t)row0 * N + p)       = __floats2half2_rn(v0, v1);
                *(half2*)(Ch + (size_t)(row0 + 8) * N + p) = __floats2half2_rn(v2, v3);
            } else if (MODE == 3) {
                *(half2*)(Ch + (size_t)row0 * N + col)       = __floats2half2_rn(v0, v1);
                *(half2*)(Ch + (size_t)(row0 + 8) * N + col) = __floats2half2_rn(v2, v3);
            } else {
                if (MODE == 2) {
                    const float g0 = gate[bb_i * 6144 + col];
                    const float g1 = gate[bb_i * 6144 + col + 1];
                    const float2 r0 = *(const float2*)(res + (size_t)row0 * N + col);
                    const float2 r1 = *(const float2*)(res + (size_t)(row0 + 8) * N + col);
                    v0 = r0.x + g0 * v0;  v1 = r0.y + g1 * v1;
                    v2 = r1.x + g0 * v2;  v3 = r1.y + g1 * v3;
                }
                *(float2*)(C + (size_t)row0 * N + col)       = make_float2(v0, v1);
                *(float2*)(C + (size_t)(row0 + 8) * N + col) = make_float2(v2, v3);
            }
        }
    }
}

// ---------------------------------------------------------------------------
// Kernel 5: windowed attention. 2 CTAs/SM, single-buffered tiles (96 KB),
// cross-CTA latency hiding. 512 CTAs x 4 tiles. rope in smem.
// ---------------------------------------------------------------------------
#define AT_TILES 4
#define AT_BUF  98304                    // 3 x 128 x 256B
#define ATTN_SMEM_BYTES AT_BUF

__global__ void __launch_bounds__(256, 2) attn_kernel(
    const __half* __restrict__ qkv, __half* __restrict__ obuf,
    const float2* __restrict__ rope)
{
    extern __shared__ char sha[];
    const uint32_t sm_u = smem_u32(sha);

    const int tid  = threadIdx.x;
    const int lane = tid & 31, warp = tid >> 5;
    const int tig  = lane & 3;
    const int tbase = blockIdx.x * AT_TILES;

    const int s_row = tid >> 4, s_ch = tid & 15;

    auto stage = [&](int tile) {
        const int w = tile >> 3, h = tile & 7;
        const size_t rb = (size_t)w * 128;
        const __half* base = qkv + (rb + s_row) * 3072 + h * 128 + s_ch * 8;
        #pragma unroll
        for (int i = 0; i < 8; i++) {
            const int r = s_row + i * 16;
            const uint32_t off = r * 256 + ((s_ch ^ (r & 7)) << 4);
            const __half* src = base + (size_t)i * 16 * 3072;
            cp16(sm_u + off,         src);
            cp16(sm_u + 32768 + off, src + 1024);
            cp16(sm_u + 65536 + off, src + 2048);
        }
    };

    const int m0 = warp * 16;
    const int l7 = lane & 7;
    const int a_row = m0 + l7 + ((lane & 8) ? 8 : 0);
    const int a_kc8 = (lane & 16) ? 1 : 0;
    const int b_row = l7 + ((lane & 16) ? 8 : 0);
    const int b_kc8 = (lane & 8) ? 1 : 0;
    const int v_row = l7 + ((lane & 8) ? 8 : 0);
    const int v_dc8 = (lane & 16) ? 1 : 0;

    const uint32_t q_u = sm_u;
    const uint32_t k_u = sm_u + 32768;
    const uint32_t v_u = sm_u + 65536;

    for (int t = 0; t < AT_TILES; t++) {
        if (t > 0) __syncthreads();        // all reads of smem done
        stage(tbase + t);
        CP_COMMIT();
        CP_WAIT0();
        __syncthreads();

        const int tile = tbase + t;
        const int h = tile & 7;
        const size_t rowbase = (size_t)(tile >> 3) * 128;

        // ---- rope in place on Q and K ----
        #pragma unroll
        for (int it = 0; it < 16; it++) {
            const int task = tid + it * 256;
            const int i  = task >> 5;
            const int dp = task & 31;
            const int d  = dp << 1;
            const int clo = (d >> 3) ^ (i & 7);
            const int chi = ((d + 64) >> 3) ^ (i & 7);
            const int ib  = (d << 1) & 15;
            const uint32_t lo = i * 256 + (clo << 4) + ib;
            const uint32_t hi = i * 256 + (chi << 4) + ib;
            const float2 sc_lo = rope[i * 64 + dp];
            const float2 sc_hi = rope[i * 64 + dp + 32];
            {
                half2* plo = (half2*)(sha + lo);
                half2* phi = (half2*)(sha + hi);
                float2 a = __half22float2(*plo);
                float2 b = __half22float2(*phi);
                *plo = __floats2half2_rn(a.x * sc_lo.y - b.x * sc_lo.x,
                                         a.y * sc_lo.y - b.y * sc_lo.x);
                *phi = __floats2half2_rn(b.x * sc_hi.y + a.x * sc_hi.x,
                                         b.y * sc_hi.y + a.y * sc_hi.x);
            }
            {
                half2* plo = (half2*)(sha + 32768 + lo);
                half2* phi = (half2*)(sha + 32768 + hi);
                float2 a = __half22float2(*plo);
                float2 b = __half22float2(*phi);
                *plo = __floats2half2_rn(a.x * sc_lo.y - b.x * sc_lo.x,
                                         a.y * sc_lo.y - b.y * sc_lo.x);
                *phi = __floats2half2_rn(b.x * sc_hi.y + a.x * sc_hi.x,
                                         b.y * sc_hi.y + a.y * sc_hi.x);
            }
        }
        __syncthreads();

        // ---- scores: S = Q K^T ----
        float acc[16][4];
        #pragma unroll
        for (int nt = 0; nt < 16; nt++)
            #pragma unroll
            for (int i = 0; i < 4; i++) acc[nt][i] = 0.f;

        #pragma unroll
        for (int kc = 0; kc < 8; kc++) {
            uint32_t a0, a1, a2, a3;
            const int ca = (kc * 2 + a_kc8) ^ (a_row & 7);
            ldsm_x4(a0, a1, a2, a3, q_u + a_row * 256 + (ca << 4));
            #pragma unroll
            for (int np = 0; np < 8; np++) {
                const int row = np * 16 + b_row;
                const int cb = (kc * 2 + b_kc8) ^ (row & 7);
                uint32_t b0, b1, c0, c1;
                ldsm_x4(b0, b1, c0, c1, k_u + row * 256 + (cb << 4));
                mma16(acc[2 * np],     a0, a1, a2, a3, b0, b1);
                mma16(acc[2 * np + 1], a0, a1, a2, a3, c0, c1);
            }
        }

        // ---- softmax ----
        const float scl = 0.08838834764831845f;
        float mx0 = -1e30f, mx1 = -1e30f;
        #pragma unroll
        for (int nt = 0; nt < 16; nt++) {
            acc[nt][0] *= scl; acc[nt][1] *= scl;
            acc[nt][2] *= scl; acc[nt][3] *= scl;
            mx0 = fmaxf(mx0, fmaxf(acc[nt][0], acc[nt][1]));
            mx1 = fmaxf(mx1, fmaxf(acc[nt][2], acc[nt][3]));
        }
        mx0 = fmaxf(mx0, __shfl_xor_sync(0xffffffffu, mx0, 1));
        mx0 = fmaxf(mx0, __shfl_xor_sync(0xffffffffu, mx0, 2));
        mx1 = fmaxf(mx1, __shfl_xor_sync(0xffffffffu, mx1, 1));
        mx1 = fmaxf(mx1, __shfl_xor_sync(0xffffffffu, mx1, 2));

        float s0 = 0.f, s1 = 0.f;
        #pragma unroll
        for (int nt = 0; nt < 16; nt++) {
            acc[nt][0] = __expf(acc[nt][0] - mx0);
            acc[nt][1] = __expf(acc[nt][1] - mx0);
            acc[nt][2] = __expf(acc[nt][2] - mx1);
            acc[nt][3] = __expf(acc[nt][3] - mx1);
            s0 += acc[nt][0] + acc[nt][1];
            s1 += acc[nt][2] + acc[nt][3];
        }
        s0 += __shfl_xor_sync(0xffffffffu, s0, 1);
        s0 += __shfl_xor_sync(0xffffffffu, s0, 2);
        s1 += __shfl_xor_sync(0xffffffffu, s1, 1);
        s1 += __shfl_xor_sync(0xffffffffu, s1, 2);
        const float i0 = 1.f / s0, i1 = 1.f / s1;

        // ---- O = P V ----
        float o[16][4];
        #pragma unroll
        for (int nt = 0; nt < 16; nt++)
            #pragma unroll
            for (int i = 0; i < 4; i++) o[nt][i] = 0.f;

        #pragma unroll
        for (int kc = 0; kc < 8; kc++) {
            const uint32_t a0 = h2u(__floats2half2_rn(acc[2 * kc][0] * i0, acc[2 * kc][1] * i0));
            const uint32_t a1 = h2u(__floats2half2_rn(acc[2 * kc][2] * i1, acc[2 * kc][3] * i1));
            const uint32_t a2 = h2u(__floats2half2_rn(acc[2 * kc + 1][0] * i0, acc[2 * kc + 1][1] * i0));
            const uint32_t a3 = h2u(__floats2half2_rn(acc[2 * kc + 1][2] * i1, acc[2 * kc + 1][3] * i1));
            #pragma unroll
            for (int dp = 0; dp < 8; dp++) {
                const int row = kc * 16 + v_row;
                const int cv = (dp * 2 + v_dc8) ^ (row & 7);
                uint32_t b0, b1, c0, c1;
                ldsm_x4t(b0, b1, c0, c1, v_u + row * 256 + (cv << 4));
                mma16(o[2 * dp],     a0, a1, a2, a3, b0, b1);
                mma16(o[2 * dp + 1], a0, a1, a2, a3, c0, c1);
            }
        }

        // ---- store O as fp16 perm64 ----
        const int gq = lane >> 2;
        #pragma unroll
        for (int nt = 0; nt < 16; nt++) {
            const int col = h * 128 + nt * 8 + (tig << 1);
            const int p = perm64c(col);
            *(half2*)(obuf + (rowbase + m0 + gq) * 1024 + p) =
                __floats2half2_rn(o[nt][0], o[nt][1]);
            *(half2*)(obuf + (rowbase + m0 + gq + 8) * 1024 + p) =
                __floats2half2_rn(o[nt][2], o[nt][3]);
        }
    }
}

// ---------------------------------------------------------------------------
// host launcher
// ---------------------------------------------------------------------------
extern "C" void kernel_launch(void* const* d_in, const int* in_sizes, int n_in,
                              void* d_out, int out_size)
{
    const float* group_x = (const float*)d_in[0];
    const float* context = (const float*)d_in[1];
    const float* W_ada   = (const float*)d_in[2];
    const float* b_ada   = (const float*)d_in[3];
    const float* scale1  = (const float*)d_in[4];
    const float* W_qkv   = (const float*)d_in[5];
    const float* b_qkv   = (const float*)d_in[6];
    const float* W_out   = (const float*)d_in[7];
    const float* b_out   = (const float*)d_in[8];
    const float* scale2  = (const float*)d_in[9];
    const float* W_ff1   = (const float*)d_in[10];
    const float* b_ff1   = (const float*)d_in[11];
    const float* W_ff2   = (const float*)d_in[12];
    const float* b_ff2   = (const float*)d_in[13];
    float* out = (float*)d_out;

    float *ada, *res2;
    __half *x1, *qkv, *obuf, *hbuf, *h1, *wqkv, *wout, *wff1, *wff2;
    float2* rope;
    cudaGetSymbolAddress((void**)&ada,  g_ada);
    cudaGetSymbolAddress((void**)&x1,   g_x1);
    cudaGetSymbolAddress((void**)&qkv,  g_qkv);
    cudaGetSymbolAddress((void**)&obuf, g_o);
    cudaGetSymbolAddress((void**)&res2, g_res);
    cudaGetSymbolAddress((void**)&hbuf, g_h);
    cudaGetSymbolAddress((void**)&h1,   g_h1);
    cudaGetSymbolAddress((void**)&rope, g_rope);
    cudaGetSymbolAddress((void**)&wqkv, g_wqkv);
    cudaGetSymbolAddress((void**)&wout, g_wout);
    cudaGetSymbolAddress((void**)&wff1, g_wff1);
    cudaGetSymbolAddress((void**)&wff2, g_wff2);

    cudaFuncSetAttribute(gemm_fp16<1>, cudaFuncAttributeMaxDynamicSharedMemorySize, GEMM_SMEM);
    cudaFuncSetAttribute(gemm_fp16<2>, cudaFuncAttributeMaxDynamicSharedMemorySize, GEMM_SMEM);
    cudaFuncSetAttribute(gemm_fp16<3>, cudaFuncAttributeMaxDynamicSharedMemorySize, GEMM_SMEM);
    cudaFuncSetAttribute(attn_kernel,  cudaFuncAttributeMaxDynamicSharedMemorySize, ATTN_SMEM_BYTES);

    const dim3 tb(32, 8);
    // order: our 4th launch = qkv GEMM (for ncu -s 5 -c 1 to land on a GEMM)
    ada_kernel<<<24, 256>>>(context, W_ada, b_ada, ada);                          // 1
    transpose_round<<<dim3(3072 / 32, 1024 / 32), tb>>>(W_qkv, wqkv, 1024, 3072); // 2
    norm_mod<<<32768, 256>>>(group_x, scale1, ada, 0, 1024, x1);                  // 3

    // 4: qkv = x1 @ W_qkv + b_qkv -> fp16 natural   (N=3072, K=1024)
    gemm_fp16<3><<<dim3(12, 256), 256, GEMM_SMEM>>>(x1, wqkv, b_qkv, nullptr, qkv,
                                                    3072, 1024, nullptr, nullptr);

    rope_kernel<<<32, 256>>>(rope);                                               // 5
    transpose_round<<<dim3(1024 / 32, 1024 / 32), tb>>>(W_out, wout, 1024, 1024); // 6
    transpose_round<<<dim3(4096 / 32, 1024 / 32), tb>>>(W_ff1, wff1, 1024, 4096); // 7
    transpose_round<<<dim3(1024 / 32, 4096 / 32), tb>>>(W_ff2, wff2, 4096, 1024); // 8

    attn_kernel<<<512, 256, ATTN_SMEM_BYTES>>>(qkv, obuf, rope);                  // 9

    // res2 = group_x + g_msa * (obuf @ W_out + b_out)   (N=1024, K=1024)
    gemm_fp16<2><<<dim3(4, 256), 256, GEMM_SMEM>>>(obuf, wout, b_out, res2, nullptr,
                                                   1024, 1024, group_x, ada + 2048);
    norm_mod<<<32768, 256>>>(res2, scale2, ada, 3072, 4096, hbuf);

    // h1 = gelu(hbuf @ W_ff1 + b_ff1) -> fp16 perm64  (N=4096, K=1024)
    gemm_fp16<1><<<dim3(16, 256), 256, GEMM_SMEM>>>(hbuf, wff1, b_ff1, nullptr, h1,
                                                    4096, 1024, nullptr, nullptr);
    // out = res2 + g_mlp * (h1 @ W_ff2 + b_ff2)        (N=1024, K=4096)
    gemm_fp16<2><<<dim3(4, 256), 256, GEMM_SMEM>>>(h1, wff2, b_ff2, out, nullptr,
                                                   1024, 4096, res2, ada + 5120);
}

// round 12
// speedup vs baseline: 1.0828x; 1.0006x over previous
#include <cuda_runtime.h>
#include <cuda_fp16.h>
#include <cstdint>

// ---------------------------------------------------------------------------
// B=8, L=4096, D=1024, H=8, DH=128, WIN=128; M = 32768.
// GEMMs: mma.sync m16n8k16 fp16 fp32-acc — tensor pipe saturated (~52% of
// ncu's fp16-acc-normalized peak = the fp32-acc rate limit). R11 config.
// Attention: persistent 296 CTAs (2/SM), single 96KB buffer, packed-P regs,
// O-store overlapped with next tile's cp.async fill.
// ---------------------------------------------------------------------------

__device__ float  g_ada [8 * 6144];
__device__ __half g_x1  [33554432];
__device__ __half g_qkv [100663296];
__device__ __half g_o   [33554432];
__device__ float  g_res [33554432];
__device__ __half g_h   [33554432];
__device__ __half g_h1  [134217728];
__device__ float2 g_rope[8192];
__device__ __half g_wqkv[3145728];
__device__ __half g_wout[1048576];
__device__ __half g_wff1[4194304];
__device__ __half g_wff2[4194304];

// ---------------------------------------------------------------------------
// helpers
// ---------------------------------------------------------------------------
__device__ __forceinline__ float gelu_tanh(float x) {
    float u = 0.7978845608028654f * (x + 0.044715f * x * x * x);
    return 0.5f * x * (1.f + tanhf(u));
}

__device__ __forceinline__ uint32_t smem_u32(const void* p) {
    uint32_t a;
    asm("{ .reg .u64 t; cvta.to.shared.u64 t, %1; cvt.u32.u64 %0, t; }" : "=r"(a) : "l"(p));
    return a;
}

__device__ __forceinline__ uint32_t h2u(half2 h) {
    uint32_t u;
    memcpy(&u, &h, 4);
    return u;
}

// perm64 operand layout: applied to BOTH A and B k-dims (dot-product invariant)
__device__ __forceinline__ int perm64h(int k) {
    const int base  = k & ~63;
    const int sb    = (k >> 5) & 1;
    const int b16   = (k >> 4) & 1;
    const int j     = (k & 15) >> 1;
    const int owner = j & 3, hi = j >> 2;
    return base + (owner * 2 + sb) * 8 + b16 * 4 + hi * 2 + (k & 1);
}
__device__ __forceinline__ int perm64c(int col) { return perm64h(col); }

__device__ __forceinline__ void mma16(float* d, uint32_t a0, uint32_t a1,
                                      uint32_t a2, uint32_t a3,
                                      uint32_t b0, uint32_t b1) {
    asm volatile(
        "mma.sync.aligned.m16n8k16.row.col.f32.f16.f16.f32 "
        "{%0,%1,%2,%3}, {%4,%5,%6,%7}, {%8,%9}, {%0,%1,%2,%3};"
        : "+f"(d[0]), "+f"(d[1]), "+f"(d[2]), "+f"(d[3])
        : "r"(a0), "r"(a1), "r"(a2), "r"(a3), "r"(b0), "r"(b1));
}

__device__ __forceinline__ void ldsm_x4(uint32_t& r0, uint32_t& r1,
                                        uint32_t& r2, uint32_t& r3, uint32_t a) {
    asm volatile("ldmatrix.sync.aligned.m8n8.x4.shared.b16 {%0,%1,%2,%3}, [%4];"
                 : "=r"(r0), "=r"(r1), "=r"(r2), "=r"(r3) : "r"(a));
}
__device__ __forceinline__ void ldsm_x4t(uint32_t& r0, uint32_t& r1,
                                         uint32_t& r2, uint32_t& r3, uint32_t a) {
    asm volatile("ldmatrix.sync.aligned.m8n8.x4.trans.shared.b16 {%0,%1,%2,%3}, [%4];"
                 : "=r"(r0), "=r"(r1), "=r"(r2), "=r"(r3) : "r"(a));
}

__device__ __forceinline__ uint4 lds128(uint32_t a) {
    uint4 v;
    asm volatile("ld.shared.v4.u32 {%0,%1,%2,%3}, [%4];"
                 : "=r"(v.x), "=r"(v.y), "=r"(v.z), "=r"(v.w) : "r"(a));
    return v;
}

__device__ __forceinline__ void cp16(uint32_t dst, const void* src) {
    asm volatile("cp.async.cg.shared.global [%0], [%1], 16;" :: "r"(dst), "l"(src));
}
#define CP_COMMIT() asm volatile("cp.async.commit_group;" ::: "memory")
#define CP_WAIT1()  asm volatile("cp.async.wait_group 1;"  ::: "memory")
#define CP_WAIT0()  asm volatile("cp.async.wait_group 0;"  ::: "memory")

// ---------------------------------------------------------------------------
// Kernel 0: Wt[n][perm64(k)] = fp16(W[k][n])
// ---------------------------------------------------------------------------
__global__ void __launch_bounds__(256) transpose_round(
    const float* __restrict__ W, __half* __restrict__ Wt, int K, int N)
{
    __shared__ float t[32][33];
    const int kb = blockIdx.y * 32, nb = blockIdx.x * 32;
    const int tx = threadIdx.x, ty = threadIdx.y;
    #pragma unroll
    for (int i = 0; i < 4; i++)
        t[ty + 8 * i][tx] = W[(size_t)(kb + ty + 8 * i) * N + nb + tx];
    __syncthreads();
    #pragma unroll
    for (int i = 0; i < 4; i++)
        Wt[(size_t)(nb + ty + 8 * i) * K + perm64h(kb + tx)] =
            __float2half_rn(t[tx][ty + 8 * i]);
}

// ---------------------------------------------------------------------------
// Kernel 1: fused  ada = silu(ctx)@W_ada + b_ada  (blocks 0..23)
//                  rope table                     (blocks 24..55)
// ---------------------------------------------------------------------------
__global__ void __launch_bounds__(256) ada_rope_kernel(
    const float* __restrict__ ctx, const float* __restrict__ W,
    const float* __restrict__ bias, float* __restrict__ ada,
    float2* __restrict__ rope)
{
    if (blockIdx.x >= 24) {
        int idx = (blockIdx.x - 24) * 256 + threadIdx.x;
        if (idx < 8192) {
            int pos = idx >> 6;
            int i   = idx & 63;
            float freq = powf(10000.f, -(float)(2 * i) / 128.f);
            float ang  = (float)pos * freq;
            rope[idx] = make_float2(sinf(ang), cosf(ang));
        }
        return;
    }
    __shared__ float sctx[8 * 1024];
    for (int i = threadIdx.x; i < 8192; i += 256) {
        float c = ctx[i];
        sctx[i] = c / (1.f + __expf(-c));
    }
    __syncthreads();
    const int col = blockIdx.x * 256 + threadIdx.x;
    float acc[8] = {0, 0, 0, 0, 0, 0, 0, 0};
    for (int k = 0; k < 1024; k++) {
        float w = W[(size_t)k * 6144 + col];
        #pragma unroll
        for (int b = 0; b < 8; b++) acc[b] += sctx[b * 1024 + k] * w;
    }
    float bv = bias[col];
    #pragma unroll
    for (int b = 0; b < 8; b++) ada[b * 6144 + col] = acc[b] + bv;
}

// ---------------------------------------------------------------------------
// Kernel 3: rmsnorm + modulate -> fp16 perm64
// ---------------------------------------------------------------------------
__global__ void __launch_bounds__(256) norm_mod(
    const float* __restrict__ x, const float* __restrict__ scale,
    const float* __restrict__ ada, int shOff, int scOff,
    __half* __restrict__ y)
{
    const int row = blockIdx.x;
    const int b   = row >> 12;
    const float4 v = ((const float4*)(x + (size_t)row * 1024))[threadIdx.x];

    float ss = v.x * v.x + v.y * v.y + v.z * v.z + v.w * v.w;
    #pragma unroll
    for (int o = 16; o > 0; o >>= 1) ss += __shfl_xor_sync(0xffffffffu, ss, o);
    __shared__ float ws[8];
    if ((threadIdx.x & 31) == 0) ws[threadIdx.x >> 5] = ss;
    __syncthreads();
    float tot = 0.f;
    #pragma unroll
    for (int i = 0; i < 8; i++) tot += ws[i];
    const float r = rsqrtf(tot * (1.f / 1024.f) + 1e-5f);

    const int c = threadIdx.x * 4;
    const float* ab = ada + b * 6144;
    const float4 s   = *(const float4*)(scale + c);
    const float4 sh  = *(const float4*)(ab + shOff + c);
    const float4 scm = *(const float4*)(ab + scOff + c);
    float o0 = v.x * r * s.x * (1.f + scm.x) + sh.x;
    float o1 = v.y * r * s.y * (1.f + scm.y) + sh.y;
    float o2 = v.z * r * s.z * (1.f + scm.z) + sh.z;
    float o3 = v.w * r * s.w * (1.f + scm.w) + sh.w;
    __half* yr = y + (size_t)row * 1024;
    *(half2*)(yr + perm64c(c))     = __floats2half2_rn(o0, o1);
    *(half2*)(yr + perm64c(c + 2)) = __floats2half2_rn(o2, o3);
}

// ---------------------------------------------------------------------------
// Kernel 4: fp16 GEMM (R11 config, pipe-saturated — unchanged)
// ---------------------------------------------------------------------------
#define STAGE_BYTES 49152            // A: 128*128 + B: 256*128
#define GEMM_SMEM  (3 * STAGE_BYTES)

template <int MODE>
__global__ void __launch_bounds__(256, 1) gemm_fp16(
    const __half* __restrict__ A, const __half* __restrict__ Bt,
    const float* __restrict__ bias,
    float* __restrict__ C, __half* __restrict__ Ch,
    int N, int K,
    const float* __restrict__ res, const float* __restrict__ gate)
{
    extern __shared__ char smem[];
    const uint32_t sm_u = smem_u32(smem);

    const int tid  = threadIdx.x;
    const int lane = tid & 31;
    const int warp = tid >> 5;
    const int g    = lane >> 2, tig = lane & 3;
    const int wm   = warp & 1;
    const int wn   = warp >> 1;
    const int cm   = blockIdx.y << 7;
    const int cn   = blockIdx.x << 8;
    const int KT   = K >> 6;

    const int f_row = tid >> 3;
    const int f_ch  = tid & 7;

    auto fill = [&](int kt, int s) {
        const uint32_t sb_ = sm_u + s * STAGE_BYTES;
        const __half* Ag = A + (size_t)(cm + f_row) * K + (kt << 6) + f_ch * 8;
        #pragma unroll
        for (int i = 0; i < 4; i++) {
            const int row = f_row + i * 32;
            cp16(sb_ + row * 128 + ((f_ch ^ (row & 7)) << 4),
                 Ag + (size_t)i * 32 * K);
        }
        const __half* Bg = Bt + (size_t)(cn + f_row) * K + (kt << 6) + f_ch * 8;
        #pragma unroll
        for (int i = 0; i < 8; i++) {
            const int row = f_row + i * 32;
            cp16(sb_ + 16384 + row * 128 + ((f_ch ^ (row & 7)) << 4),
                 Bg + (size_t)i * 32 * K);
        }
    };

    float acc[4][8][4];
    #pragma unroll
    for (int mt = 0; mt < 4; mt++)
        #pragma unroll
        for (int nt = 0; nt < 8; nt++)
            #pragma unroll
            for (int i = 0; i < 4; i++) acc[mt][nt][i] = 0.f;

    fill(0, 0); CP_COMMIT();
    if (KT > 1) fill(1, 1);
    CP_COMMIT();

    int s = 0;
    for (int kt = 0; kt < KT; kt++) {
        CP_WAIT1();
        __syncthreads();

        const uint32_t a_base = sm_u + s * STAGE_BYTES;
        const uint32_t b_base = a_base + 16384;
        #pragma unroll
        for (int sb = 0; sb < 2; sb++) {
            const int chn = (tig << 1) | sb;
            uint4 al[4], ah[4];
            #pragma unroll
            for (int mt = 0; mt < 4; mt++) {
                const int rl = wm * 64 + mt * 16 + g;
                al[mt] = lds128(a_base + rl * 128 + ((chn ^ (rl & 7)) << 4));
                ah[mt] = lds128(a_base + (rl + 8) * 128 + ((chn ^ (rl & 7)) << 4));
            }
            #pragma unroll
            for (int nt = 0; nt < 8; nt++) {
                const int rb = wn * 64 + nt * 8 + g;
                const uint4 bb = lds128(b_base + rb * 128 + ((chn ^ (rb & 7)) << 4));
                #pragma unroll
                for (int mt = 0; mt < 4; mt++) {
                    mma16(acc[mt][nt], al[mt].x, ah[mt].x, al[mt].y, ah[mt].y,
                          bb.x, bb.y);
                    mma16(acc[mt][nt], al[mt].z, ah[mt].z, al[mt].w, ah[mt].w,
                          bb.z, bb.w);
                }
            }
        }
        if (kt + 2 < KT) fill(kt + 2, (s + 2 >= 3) ? s - 1 : s + 2);
        CP_COMMIT();
        s = (s + 1 == 3) ? 0 : s + 1;
    }

    const int bb_i = cm >> 12;
    #pragma unroll
    for (int mt = 0; mt < 4; mt++) {
        const int row0 = cm + wm * 64 + mt * 16 + g;
        #pragma unroll
        for (int nt = 0; nt < 8; nt++) {
            const int col = cn + wn * 64 + nt * 8 + (tig << 1);
            const float bi0 = bias[col], bi1 = bias[col + 1];
            float v0 = acc[mt][nt][0] + bi0;
            float v1 = acc[mt][nt][1] + bi1;
            float v2 = acc[mt][nt][2] + bi0;
            float v3 = acc[mt][nt][3] + bi1;
            if (MODE == 1) {
                v0 = gelu_tanh(v0); v1 = gelu_tanh(v1);
                v2 = gelu_tanh(v2); v3 = gelu_tanh(v3);
                const int p = perm64c(col);
                *(half2*)(Ch + (size_t)row0 * N + p)       = __floats2half2_rn(v0, v1);
                *(half2*)(Ch + (size_t)(row0 + 8) * N + p) = __floats2half2_rn(v2, v3);
            } else if (MODE == 3) {
                *(half2*)(Ch + (size_t)row0 * N + col)       = __floats2half2_rn(v0, v1);
                *(half2*)(Ch + (size_t)(row0 + 8) * N + col) = __floats2half2_rn(v2, v3);
            } else {
                if (MODE == 2) {
                    const float g0 = gate[bb_i * 6144 + col];
                    const float g1 = gate[bb_i * 6144 + col + 1];
                    const float2 r0 = *(const float2*)(res + (size_t)row0 * N + col);
                    const float2 r1 = *(const float2*)(res + (size_t)(row0 + 8) * N + col);
                    v0 = r0.x + g0 * v0;  v1 = r0.y + g1 * v1;
                    v2 = r1.x + g0 * v2;  v3 = r1.y + g1 * v3;
                }
                *(float2*)(C + (size_t)row0 * N + col)       = make_float2(v0, v1);
                *(float2*)(C + (size_t)(row0 + 8) * N + col) = make_float2(v2, v3);
            }
        }
    }
}

// ---------------------------------------------------------------------------
// Kernel 5: persistent windowed attention. 296 CTAs (2/SM), single 96KB
// buffer, packed-P registers, O-store overlapped with next tile's fill.
// ---------------------------------------------------------------------------
#define AT_BUF  98304
#define ATTN_SMEM_BYTES AT_BUF
#define AT_NTILES 2048
#define AT_GRID   296

__global__ void __launch_bounds__(256, 2) attn_kernel(
    const __half* __restrict__ qkv, __half* __restrict__ obuf,
    const float2* __restrict__ rope)
{
    extern __shared__ char sha[];
    const uint32_t sm_u = smem_u32(sha);

    const int tid  = threadIdx.x;
    const int lane = tid & 31, warp = tid >> 5;
    const int tig  = lane & 3;

    const int s_row = tid >> 4, s_ch = tid & 15;

    auto stage = [&](int tile) {
        const int w = tile >> 3, h = tile & 7;
        const size_t rb = (size_t)w * 128;
        const __half* base = qkv + (rb + s_row) * 3072 + h * 128 + s_ch * 8;
        #pragma unroll
        for (int i = 0; i < 8; i++) {
            const int r = s_row + i * 16;
            const uint32_t off = r * 256 + ((s_ch ^ (r & 7)) << 4);
            const __half* src = base + (size_t)i * 16 * 3072;
            cp16(sm_u + off,         src);
            cp16(sm_u + 32768 + off, src + 1024);
            cp16(sm_u + 65536 + off, src + 2048);
        }
    };

    const int m0 = warp * 16;
    const int l7 = lane & 7;
    const int a_row = m0 + l7 + ((lane & 8) ? 8 : 0);
    const int a_kc8 = (lane & 16) ? 1 : 0;
    const int b_row = l7 + ((lane & 16) ? 8 : 0);
    const int b_kc8 = (lane & 8) ? 1 : 0;
    const int v_row = l7 + ((lane & 8) ? 8 : 0);
    const int v_dc8 = (lane & 16) ? 1 : 0;

    const uint32_t q_u = sm_u;
    const uint32_t k_u = sm_u + 32768;
    const uint32_t v_u = sm_u + 65536;

    stage(blockIdx.x); CP_COMMIT();

    for (int tile = blockIdx.x; tile < AT_NTILES; tile += AT_GRID) {
        CP_WAIT0();
        __syncthreads();

        const int h = tile & 7;
        const size_t rowbase = (size_t)(tile >> 3) * 128;

        // ---- rope in place on Q and K ----
        #pragma unroll
        for (int it = 0; it < 16; it++) {
            const int task = tid + it * 256;
            const int i  = task >> 5;
            const int dp = task & 31;
            const int d  = dp << 1;
            const int clo = (d >> 3) ^ (i & 7);
            const int chi = ((d + 64) >> 3) ^ (i & 7);
            const int ib  = (d << 1) & 15;
            const uint32_t lo = i * 256 + (clo << 4) + ib;
            const uint32_t hi = i * 256 + (chi << 4) + ib;
            const float2 sc_lo = rope[i * 64 + dp];
            const float2 sc_hi = rope[i * 64 + dp + 32];
            {
                half2* plo = (half2*)(sha + lo);
                half2* phi = (half2*)(sha + hi);
                float2 a = __half22float2(*plo);
                float2 b = __half22float2(*phi);
                *plo = __floats2half2_rn(a.x * sc_lo.y - b.x * sc_lo.x,
                                         a.y * sc_lo.y - b.y * sc_lo.x);
                *phi = __floats2half2_rn(b.x * sc_hi.y + a.x * sc_hi.x,
                                         b.y * sc_hi.y + a.y * sc_hi.x);
            }
            {
                half2* plo = (half2*)(sha + 32768 + lo);
                half2* phi = (half2*)(sha + 32768 + hi);
                float2 a = __half22float2(*plo);
                float2 b = __half22float2(*phi);
                *plo = __floats2half2_rn(a.x * sc_lo.y - b.x * sc_lo.x,
                                         a.y * sc_lo.y - b.y * sc_lo.x);
                *phi = __floats2half2_rn(b.x * sc_hi.y + a.x * sc_hi.x,
                                         b.y * sc_hi.y + a.y * sc_hi.x);
            }
        }
        __syncthreads();

        // ---- scores: S = Q K^T ----
        float acc[16][4];
        #pragma unroll
        for (int nt = 0; nt < 16; nt++)
            #pragma unroll
            for (int i = 0; i < 4; i++) acc[nt][i] = 0.f;

        #pragma unroll
        for (int kc = 0; kc < 8; kc++) {
            uint32_t a0, a1, a2, a3;
            const int ca = (kc * 2 + a_kc8) ^ (a_row & 7);
            ldsm_x4(a0, a1, a2, a3, q_u + a_row * 256 + (ca << 4));
            #pragma unroll
            for (int np = 0; np < 8; np++) {
                const int row = np * 16 + b_row;
                const int cb = (kc * 2 + b_kc8) ^ (row & 7);
                uint32_t b0, b1, c0, c1;
                ldsm_x4(b0, b1, c0, c1, k_u + row * 256 + (cb << 4));
                mma16(acc[2 * np],     a0, a1, a2, a3, b0, b1);
                mma16(acc[2 * np + 1], a0, a1, a2, a3, c0, c1);
            }
        }

        // ---- softmax ----
        const float scl = 0.08838834764831845f;
        float mx0 = -1e30f, mx1 = -1e30f;
        #pragma unroll
        for (int nt = 0; nt < 16; nt++) {
            acc[nt][0] *= scl; acc[nt][1] *= scl;
            acc[nt][2] *= scl; acc[nt][3] *= scl;
            mx0 = fmaxf(mx0, fmaxf(acc[nt][0], acc[nt][1]));
            mx1 = fmaxf(mx1, fmaxf(acc[nt][2], acc[nt][3]));
        }
        mx0 = fmaxf(mx0, __shfl_xor_sync(0xffffffffu, mx0, 1));
        mx0 = fmaxf(mx0, __shfl_xor_sync(0xffffffffu, mx0, 2));
        mx1 = fmaxf(mx1, __shfl_xor_sync(0xffffffffu, mx1, 1));
        mx1 = fmaxf(mx1, __shfl_xor_sync(0xffffffffu, mx1, 2));

        float s0 = 0.f, s1 = 0.f;
        #pragma unroll
        for (int nt = 0; nt < 16; nt++) {
            acc[nt][0] = __expf(acc[nt][0] - mx0);
            acc[nt][1] = __expf(acc[nt][1] - mx0);
            acc[nt][2] = __expf(acc[nt][2] - mx1);
            acc[nt][3] = __expf(acc[nt][3] - mx1);
            s0 += acc[nt][0] + acc[nt][1];
            s1 += acc[nt][2] + acc[nt][3];
        }
        s0 += __shfl_xor_sync(0xffffffffu, s0, 1);
        s0 += __shfl_xor_sync(0xffffffffu, s0, 2);
        s1 += __shfl_xor_sync(0xffffffffu, s1, 1);
        s1 += __shfl_xor_sync(0xffffffffu, s1, 2);
        const float i0 = 1.f / s0, i1 = 1.f / s1;

        // ---- pack P into 32 regs (frees acc registers before PV) ----
        uint32_t p[32];
        #pragma unroll
        for (int kc = 0; kc < 8; kc++) {
            p[4 * kc + 0] = h2u(__floats2half2_rn(acc[2 * kc][0] * i0, acc[2 * kc][1] * i0));
            p[4 * kc + 1] = h2u(__floats2half2_rn(acc[2 * kc][2] * i1, acc[2 * kc][3] * i1));
            p[4 * kc + 2] = h2u(__floats2half2_rn(acc[2 * kc + 1][0] * i0, acc[2 * kc + 1][1] * i0));
            p[4 * kc + 3] = h2u(__floats2half2_rn(acc[2 * kc + 1][2] * i1, acc[2 * kc + 1][3] * i1));
        }

        // ---- O = P V ----
        float o[16][4];
        #pragma unroll
        for (int nt = 0; nt < 16; nt++)
            #pragma unroll
            for (int i = 0; i < 4; i++) o[nt][i] = 0.f;

        #pragma unroll
        for (int kc = 0; kc < 8; kc++) {
            #pragma unroll
            for (int dp = 0; dp < 8; dp++) {
                const int row = kc * 16 + v_row;
                const int cv = (dp * 2 + v_dc8) ^ (row & 7);
                uint32_t b0, b1, c0, c1;
                ldsm_x4t(b0, b1, c0, c1, v_u + row * 256 + (cv << 4));
                mma16(o[2 * dp],     p[4 * kc], p[4 * kc + 1], p[4 * kc + 2], p[4 * kc + 3], b0, b1);
                mma16(o[2 * dp + 1], p[4 * kc], p[4 * kc + 1], p[4 * kc + 2], p[4 * kc + 3], c0, c1);
            }
        }

        // ---- all smem reads done: start next tile's fill, then store O ----
        __syncthreads();
        if (tile + AT_GRID < AT_NTILES) stage(tile + AT_GRID);
        CP_COMMIT();

        const int gq = lane >> 2;
        #pragma unroll
        for (int nt = 0; nt < 16; nt++) {
            const int col = h * 128 + nt * 8 + (tig << 1);
            const int pc = perm64c(col);
            *(half2*)(obuf + (rowbase + m0 + gq) * 1024 + pc) =
                __floats2half2_rn(o[nt][0], o[nt][1]);
            *(half2*)(obuf + (rowbase + m0 + gq + 8) * 1024 + pc) =
                __floats2half2_rn(o[nt][2], o[nt][3]);
        }
    }
}

// ---------------------------------------------------------------------------
// host launcher
// ---------------------------------------------------------------------------
extern "C" void kernel_launch(void* const* d_in, const int* in_sizes, int n_in,
                              void* d_out, int out_size)
{
    const float* group_x = (const float*)d_in[0];
    const float* context = (const float*)d_in[1];
    const float* W_ada   = (const float*)d_in[2];
    const float* b_ada   = (const float*)d_in[3];
    const float* scale1  = (const float*)d_in[4];
    const float* W_qkv   = (const float*)d_in[5];
    const float* b_qkv   = (const float*)d_in[6];
    const float* W_out   = (const float*)d_in[7];
    const float* b_out   = (const float*)d_in[8];
    const float* scale2  = (const float*)d_in[9];
    const float* W_ff1   = (const float*)d_in[10];
    const float* b_ff1   = (const float*)d_in[11];
    const float* W_ff2   = (const float*)d_in[12];
    const float* b_ff2   = (const float*)d_in[13];
    float* out = (float*)d_out;

    float *ada, *res2;
    __half *x1, *qkv, *obuf, *hbuf, *h1, *wqkv, *wout, *wff1, *wff2;
    float2* rope;
    cudaGetSymbolAddress((void**)&ada,  g_ada);
    cudaGetSymbolAddress((void**)&x1,   g_x1);
    cudaGetSymbolAddress((void**)&qkv,  g_qkv);
    cudaGetSymbolAddress((void**)&obuf, g_o);
    cudaGetSymbolAddress((void**)&res2, g_res);
    cudaGetSymbolAddress((void**)&hbuf, g_h);
    cudaGetSymbolAddress((void**)&h1,   g_h1);
    cudaGetSymbolAddress((void**)&rope, g_rope);
    cudaGetSymbolAddress((void**)&wqkv, g_wqkv);
    cudaGetSymbolAddress((void**)&wout, g_wout);
    cudaGetSymbolAddress((void**)&wff1, g_wff1);
    cudaGetSymbolAddress((void**)&wff2, g_wff2);

    cudaFuncSetAttribute(gemm_fp16<1>, cudaFuncAttributeMaxDynamicSharedMemorySize, GEMM_SMEM);
    cudaFuncSetAttribute(gemm_fp16<2>, cudaFuncAttributeMaxDynamicSharedMemorySize, GEMM_SMEM);
    cudaFuncSetAttribute(gemm_fp16<3>, cudaFuncAttributeMaxDynamicSharedMemorySize, GEMM_SMEM);
    cudaFuncSetAttribute(attn_kernel,  cudaFuncAttributeMaxDynamicSharedMemorySize, ATTN_SMEM_BYTES);

    const dim3 tb(32, 8);
    ada_rope_kernel<<<56, 256>>>(context, W_ada, b_ada, ada, rope);               // 1
    transpose_round<<<dim3(3072 / 32, 1024 / 32), tb>>>(W_qkv, wqkv, 1024, 3072); // 2
    norm_mod<<<32768, 256>>>(group_x, scale1, ada, 0, 1024, x1);                  // 3

    // 4 (profiled): qkv = x1 @ W_qkv + b_qkv -> fp16 natural (N=3072, K=1024)
    gemm_fp16<3><<<dim3(12, 256), 256, GEMM_SMEM>>>(x1, wqkv, b_qkv, nullptr, qkv,
                                                    3072, 1024, nullptr, nullptr);

    transpose_round<<<dim3(1024 / 32, 1024 / 32), tb>>>(W_out, wout, 1024, 1024); // 5
    transpose_round<<<dim3(4096 / 32, 1024 / 32), tb>>>(W_ff1, wff1, 1024, 4096); // 6
    transpose_round<<<dim3(1024 / 32, 4096 / 32), tb>>>(W_ff2, wff2, 4096, 1024); // 7

    attn_kernel<<<AT_GRID, 256, ATTN_SMEM_BYTES>>>(qkv, obuf, rope);              // 8

    // res2 = group_x + g_msa * (obuf @ W_out + b_out)   (N=1024, K=1024)
    gemm_fp16<2><<<dim3(4, 256), 256, GEMM_SMEM>>>(obuf, wout, b_out, res2, nullptr,
                                                   1024, 1024, group_x, ada + 2048);
    norm_mod<<<32768, 256>>>(res2, scale2, ada, 3072, 4096, hbuf);

    // h1 = gelu(hbuf @ W_ff1 + b_ff1) -> fp16 perm64  (N=4096, K=1024)
    gemm_fp16<1><<<dim3(16, 256), 256, GEMM_SMEM>>>(hbuf, wff1, b_ff1, nullptr, h1,
                                                    4096, 1024, nullptr, nullptr);
    // out = res2 + g_mlp * (h1 @ W_ff2 + b_ff2)        (N=1024, K=4096)
    gemm_fp16<2><<<dim3(4, 256), 256, GEMM_SMEM>>>(h1, wff2, b_ff2, out, nullptr,
                                                   1024, 4096, res2, ada + 5120);
}

// round 13
// speedup vs baseline: 1.0892x; 1.0059x over previous
#include <cuda_runtime.h>
#include <cuda_fp16.h>
#include <cstdint>

// ---------------------------------------------------------------------------
// B=8, L=4096, D=1024, H=8, DH=128, WIN=128; M = 32768.
// GEMMs: mma.sync m16n8k16 fp16 fp32-acc (pipe-saturated at the fp32-acc
// rate, tensor=52.6% of ncu's fp16-acc-normalized peak). R11/R12 config.
// Attention: persistent 296 CTAs (2/SM) — launch #4 so ncu profiles it.
// Prep work (ada, rope, weight transposes) fused into 2 launches.
// ---------------------------------------------------------------------------

__device__ float  g_ada [8 * 6144];
__device__ __half g_x1  [33554432];
__device__ __half g_qkv [100663296];
__device__ __half g_o   [33554432];
__device__ float  g_res [33554432];
__device__ __half g_h   [33554432];
__device__ __half g_h1  [134217728];
__device__ float2 g_rope[8192];
__device__ __half g_wqkv[3145728];
__device__ __half g_wout[1048576];
__device__ __half g_wff1[4194304];
__device__ __half g_wff2[4194304];

// ---------------------------------------------------------------------------
// helpers
// ---------------------------------------------------------------------------
__device__ __forceinline__ float gelu_tanh(float x) {
    float u = 0.7978845608028654f * (x + 0.044715f * x * x * x);
    return 0.5f * x * (1.f + tanhf(u));
}

__device__ __forceinline__ uint32_t smem_u32(const void* p) {
    uint32_t a;
    asm("{ .reg .u64 t; cvta.to.shared.u64 t, %1; cvt.u32.u64 %0, t; }" : "=r"(a) : "l"(p));
    return a;
}

__device__ __forceinline__ uint32_t h2u(half2 h) {
    uint32_t u;
    memcpy(&u, &h, 4);
    return u;
}

// perm64 operand layout: applied to BOTH A and B k-dims (dot-product invariant)
__device__ __forceinline__ int perm64h(int k) {
    const int base  = k & ~63;
    const int sb    = (k >> 5) & 1;
    const int b16   = (k >> 4) & 1;
    const int j     = (k & 15) >> 1;
    const int owner = j & 3, hi = j >> 2;
    return base + (owner * 2 + sb) * 8 + b16 * 4 + hi * 2 + (k & 1);
}
__device__ __forceinline__ int perm64c(int col) { return perm64h(col); }

__device__ __forceinline__ void mma16(float* d, uint32_t a0, uint32_t a1,
                                      uint32_t a2, uint32_t a3,
                                      uint32_t b0, uint32_t b1) {
    asm volatile(
        "mma.sync.aligned.m16n8k16.row.col.f32.f16.f16.f32 "
        "{%0,%1,%2,%3}, {%4,%5,%6,%7}, {%8,%9}, {%0,%1,%2,%3};"
        : "+f"(d[0]), "+f"(d[1]), "+f"(d[2]), "+f"(d[3])
        : "r"(a0), "r"(a1), "r"(a2), "r"(a3), "r"(b0), "r"(b1));
}

__device__ __forceinline__ void ldsm_x4(uint32_t& r0, uint32_t& r1,
                                        uint32_t& r2, uint32_t& r3, uint32_t a) {
    asm volatile("ldmatrix.sync.aligned.m8n8.x4.shared.b16 {%0,%1,%2,%3}, [%4];"
                 : "=r"(r0), "=r"(r1), "=r"(r2), "=r"(r3) : "r"(a));
}
__device__ __forceinline__ void ldsm_x4t(uint32_t& r0, uint32_t& r1,
                                         uint32_t& r2, uint32_t& r3, uint32_t a) {
    asm volatile("ldmatrix.sync.aligned.m8n8.x4.trans.shared.b16 {%0,%1,%2,%3}, [%4];"
                 : "=r"(r0), "=r"(r1), "=r"(r2), "=r"(r3) : "r"(a));
}

__device__ __forceinline__ uint4 lds128(uint32_t a) {
    uint4 v;
    asm volatile("ld.shared.v4.u32 {%0,%1,%2,%3}, [%4];"
                 : "=r"(v.x), "=r"(v.y), "=r"(v.z), "=r"(v.w) : "r"(a));
    return v;
}

__device__ __forceinline__ void cp16(uint32_t dst, const void* src) {
    asm volatile("cp.async.cg.shared.global [%0], [%1], 16;" :: "r"(dst), "l"(src));
}
#define CP_COMMIT() asm volatile("cp.async.commit_group;" ::: "memory")
#define CP_WAIT1()  asm volatile("cp.async.wait_group 1;"  ::: "memory")
#define CP_WAIT0()  asm volatile("cp.async.wait_group 0;"  ::: "memory")

// ---------------------------------------------------------------------------
// device transpose helper: Wt[n][perm64(k)] = fp16(W[k][n]), 32x32 tile
// 256 threads acting as (tx = tid&31, ty = tid>>5)
// ---------------------------------------------------------------------------
__device__ __forceinline__ void dev_transpose(
    const float* __restrict__ W, __half* __restrict__ Wt,
    int K, int N, int kb, int nb, float* sh)
{
    const int tx = threadIdx.x & 31, ty = threadIdx.x >> 5;   // 32 x 8
    #pragma unroll
    for (int i = 0; i < 4; i++)
        sh[(ty + 8 * i) * 33 + tx] = W[(size_t)(kb + ty + 8 * i) * N + nb + tx];
    __syncthreads();
    #pragma unroll
    for (int i = 0; i < 4; i++)
        Wt[(size_t)(nb + ty + 8 * i) * K + perm64h(kb + tx)] =
            __float2half_rn(sh[tx * 33 + ty + 8 * i]);
}

// ---------------------------------------------------------------------------
// Kernel 1: prep = ada (blocks 0..23) + rope table (24..55)
//                + W_qkv transpose (56..3127)
// ---------------------------------------------------------------------------
__global__ void __launch_bounds__(256) prep_kernel(
    const float* __restrict__ ctx, const float* __restrict__ W_ada,
    const float* __restrict__ b_ada, float* __restrict__ ada,
    float2* __restrict__ rope,
    const float* __restrict__ W_qkv, __half* __restrict__ wqkv)
{
    __shared__ float sh[8448];
    const int b = blockIdx.x;
    if (b < 24) {
        for (int i = threadIdx.x; i < 8192; i += 256) {
            float c = ctx[i];
            sh[i] = c / (1.f + __expf(-c));
        }
        __syncthreads();
        const int col = b * 256 + threadIdx.x;
        float acc[8] = {0, 0, 0, 0, 0, 0, 0, 0};
        for (int k = 0; k < 1024; k++) {
            float w = W_ada[(size_t)k * 6144 + col];
            #pragma unroll
            for (int bb = 0; bb < 8; bb++) acc[bb] += sh[bb * 1024 + k] * w;
        }
        float bv = b_ada[col];
        #pragma unroll
        for (int bb = 0; bb < 8; bb++) ada[bb * 6144 + col] = acc[bb] + bv;
    } else if (b < 56) {
        int idx = (b - 24) * 256 + threadIdx.x;
        if (idx < 8192) {
            int pos = idx >> 6;
            int i   = idx & 63;
            float freq = powf(10000.f, -(float)(2 * i) / 128.f);
            float ang  = (float)pos * freq;
            rope[idx] = make_float2(sinf(ang), cosf(ang));
        }
    } else {
        const int t = b - 56;                 // 0..3071
        const int nb = (t % 96) * 32;
        const int kb = (t / 96) * 32;
        dev_transpose(W_qkv, wqkv, 1024, 3072, kb, nb, sh);
    }
}

// ---------------------------------------------------------------------------
// Kernel 2: rmsnorm + modulate -> fp16 perm64; extra blocks do the
// wout/wff1/wff2 transposes (norm1 launch only).
// ---------------------------------------------------------------------------
__global__ void __launch_bounds__(256) norm_mod(
    const float* __restrict__ x, const float* __restrict__ scale,
    const float* __restrict__ ada, int shOff, int scOff,
    __half* __restrict__ y,
    const float* __restrict__ W_out, __half* __restrict__ wout,
    const float* __restrict__ W_ff1, __half* __restrict__ wff1,
    const float* __restrict__ W_ff2, __half* __restrict__ wff2)
{
    __shared__ float sh[1056];
    const int row = blockIdx.x;
    if (row >= 32768) {
        int t = row - 32768;
        if (t < 1024) {
            dev_transpose(W_out, wout, 1024, 1024, (t / 32) * 32, (t % 32) * 32, sh);
        } else if (t < 5120) {
            t -= 1024;
            dev_transpose(W_ff1, wff1, 1024, 4096, (t / 128) * 32, (t % 128) * 32, sh);
        } else {
            t -= 5120;
            dev_transpose(W_ff2, wff2, 4096, 1024, (t / 32) * 32, (t % 32) * 32, sh);
        }
        return;
    }
    const int b = row >> 12;
    const float4 v = ((const float4*)(x + (size_t)row * 1024))[threadIdx.x];

    float ss = v.x * v.x + v.y * v.y + v.z * v.z + v.w * v.w;
    #pragma unroll
    for (int o = 16; o > 0; o >>= 1) ss += __shfl_xor_sync(0xffffffffu, ss, o);
    if ((threadIdx.x & 31) == 0) sh[threadIdx.x >> 5] = ss;
    __syncthreads();
    float tot = 0.f;
    #pragma unroll
    for (int i = 0; i < 8; i++) tot += sh[i];
    const float r = rsqrtf(tot * (1.f / 1024.f) + 1e-5f);

    const int c = threadIdx.x * 4;
    const float* ab = ada + b * 6144;
    const float4 s   = *(const float4*)(scale + c);
    const float4 shv = *(const float4*)(ab + shOff + c);
    const float4 scm = *(const float4*)(ab + scOff + c);
    float o0 = v.x * r * s.x * (1.f + scm.x) + shv.x;
    float o1 = v.y * r * s.y * (1.f + scm.y) + shv.y;
    float o2 = v.z * r * s.z * (1.f + scm.z) + shv.z;
    float o3 = v.w * r * s.w * (1.f + scm.w) + shv.w;
    __half* yr = y + (size_t)row * 1024;
    *(half2*)(yr + perm64c(c))     = __floats2half2_rn(o0, o1);
    *(half2*)(yr + perm64c(c + 2)) = __floats2half2_rn(o2, o3);
}

// ---------------------------------------------------------------------------
// Kernel 4: fp16 GEMM (R11 config, pipe-saturated — unchanged)
// ---------------------------------------------------------------------------
#define STAGE_BYTES 49152            // A: 128*128 + B: 256*128
#define GEMM_SMEM  (3 * STAGE_BYTES)

template <int MODE>
__global__ void __launch_bounds__(256, 1) gemm_fp16(
    const __half* __restrict__ A, const __half* __restrict__ Bt,
    const float* __restrict__ bias,
    float* __restrict__ C, __half* __restrict__ Ch,
    int N, int K,
    const float* __restrict__ res, const float* __restrict__ gate)
{
    extern __shared__ char smem[];
    const uint32_t sm_u = smem_u32(smem);

    const int tid  = threadIdx.x;
    const int lane = tid & 31;
    const int warp = tid >> 5;
    const int g    = lane >> 2, tig = lane & 3;
    const int wm   = warp & 1;
    const int wn   = warp >> 1;
    const int cm   = blockIdx.y << 7;
    const int cn   = blockIdx.x << 8;
    const int KT   = K >> 6;

    const int f_row = tid >> 3;
    const int f_ch  = tid & 7;

    auto fill = [&](int kt, int s) {
        const uint32_t sb_ = sm_u + s * STAGE_BYTES;
        const __half* Ag = A + (size_t)(cm + f_row) * K + (kt << 6) + f_ch * 8;
        #pragma unroll
        for (int i = 0; i < 4; i++) {
            const int row = f_row + i * 32;
            cp16(sb_ + row * 128 + ((f_ch ^ (row & 7)) << 4),
                 Ag + (size_t)i * 32 * K);
        }
        const __half* Bg = Bt + (size_t)(cn + f_row) * K + (kt << 6) + f_ch * 8;
        #pragma unroll
        for (int i = 0; i < 8; i++) {
            const int row = f_row + i * 32;
            cp16(sb_ + 16384 + row * 128 + ((f_ch ^ (row & 7)) << 4),
                 Bg + (size_t)i * 32 * K);
        }
    };

    float acc[4][8][4];
    #pragma unroll
    for (int mt = 0; mt < 4; mt++)
        #pragma unroll
        for (int nt = 0; nt < 8; nt++)
            #pragma unroll
            for (int i = 0; i < 4; i++) acc[mt][nt][i] = 0.f;

    fill(0, 0); CP_COMMIT();
    if (KT > 1) fill(1, 1);
    CP_COMMIT();

    int s = 0;
    for (int kt = 0; kt < KT; kt++) {
        CP_WAIT1();
        __syncthreads();

        const uint32_t a_base = sm_u + s * STAGE_BYTES;
        const uint32_t b_base = a_base + 16384;
        #pragma unroll
        for (int sb = 0; sb < 2; sb++) {
            const int chn = (tig << 1) | sb;
            uint4 al[4], ah[4];
            #pragma unroll
            for (int mt = 0; mt < 4; mt++) {
                const int rl = wm * 64 + mt * 16 + g;
                al[mt] = lds128(a_base + rl * 128 + ((chn ^ (rl & 7)) << 4));
                ah[mt] = lds128(a_base + (rl + 8) * 128 + ((chn ^ (rl & 7)) << 4));
            }
            #pragma unroll
            for (int nt = 0; nt < 8; nt++) {
                const int rb = wn * 64 + nt * 8 + g;
                const uint4 bb = lds128(b_base + rb * 128 + ((chn ^ (rb & 7)) << 4));
                #pragma unroll
                for (int mt = 0; mt < 4; mt++) {
                    mma16(acc[mt][nt], al[mt].x, ah[mt].x, al[mt].y, ah[mt].y,
                          bb.x, bb.y);
                    mma16(acc[mt][nt], al[mt].z, ah[mt].z, al[mt].w, ah[mt].w,
                          bb.z, bb.w);
                }
            }
        }
        if (kt + 2 < KT) fill(kt + 2, (s + 2 >= 3) ? s - 1 : s + 2);
        CP_COMMIT();
        s = (s + 1 == 3) ? 0 : s + 1;
    }

    const int bb_i = cm >> 12;
    #pragma unroll
    for (int mt = 0; mt < 4; mt++) {
        const int row0 = cm + wm * 64 + mt * 16 + g;
        #pragma unroll
        for (int nt = 0; nt < 8; nt++) {
            const int col = cn + wn * 64 + nt * 8 + (tig << 1);
            const float bi0 = bias[col], bi1 = bias[col + 1];
            float v0 = acc[mt][nt][0] + bi0;
            float v1 = acc[mt][nt][1] + bi1;
            float v2 = acc[mt][nt][2] + bi0;
            float v3 = acc[mt][nt][3] + bi1;
            if (MODE == 1) {
                v0 = gelu_tanh(v0); v1 = gelu_tanh(v1);
                v2 = gelu_tanh(v2); v3 = gelu_tanh(v3);
                const int p = perm64c(col);
                *(half2*)(Ch + (size_t)row0 * N + p)       = __floats2half2_rn(v0, v1);
                *(half2*)(Ch + (size_t)(row0 + 8) * N + p) = __floats2half2_rn(v2, v3);
            } else if (MODE == 3) {
                *(half2*)(Ch + (size_t)row0 * N + col)       = __floats2half2_rn(v0, v1);
                *(half2*)(Ch + (size_t)(row0 + 8) * N + col) = __floats2half2_rn(v2, v3);
            } else {
                if (MODE == 2) {
                    const float g0 = gate[bb_i * 6144 + col];
                    const float g1 = gate[bb_i * 6144 + col + 1];
                    const float2 r0 = *(const float2*)(res + (size_t)row0 * N + col);
                    const float2 r1 = *(const float2*)(res + (size_t)(row0 + 8) * N + col);
                    v0 = r0.x + g0 * v0;  v1 = r0.y + g1 * v1;
                    v2 = r1.x + g0 * v2;  v3 = r1.y + g1 * v3;
                }
                *(float2*)(C + (size_t)row0 * N + col)       = make_float2(v0, v1);
                *(float2*)(C + (size_t)(row0 + 8) * N + col) = make_float2(v2, v3);
            }
        }
    }
}

// ---------------------------------------------------------------------------
// Kernel 5: persistent windowed attention (R12 internals, launch #4)
// ---------------------------------------------------------------------------
#define AT_BUF  98304
#define ATTN_SMEM_BYTES AT_BUF
#define AT_NTILES 2048
#define AT_GRID   296

__global__ void __launch_bounds__(256, 2) attn_kernel(
    const __half* __restrict__ qkv, __half* __restrict__ obuf,
    const float2* __restrict__ rope)
{
    extern __shared__ char sha[];
    const uint32_t sm_u = smem_u32(sha);

    const int tid  = threadIdx.x;
    const int lane = tid & 31, warp = tid >> 5;
    const int tig  = lane & 3;

    const int s_row = tid >> 4, s_ch = tid & 15;

    auto stage = [&](int tile) {
        const int w = tile >> 3, h = tile & 7;
        const size_t rb = (size_t)w * 128;
        const __half* base = qkv + (rb + s_row) * 3072 + h * 128 + s_ch * 8;
        #pragma unroll
        for (int i = 0; i < 8; i++) {
            const int r = s_row + i * 16;
            const uint32_t off = r * 256 + ((s_ch ^ (r & 7)) << 4);
            const __half* src = base + (size_t)i * 16 * 3072;
            cp16(sm_u + off,         src);
            cp16(sm_u + 32768 + off, src + 1024);
            cp16(sm_u + 65536 + off, src + 2048);
        }
    };

    const int m0 = warp * 16;
    const int l7 = lane & 7;
    const int a_row = m0 + l7 + ((lane & 8) ? 8 : 0);
    const int a_kc8 = (lane & 16) ? 1 : 0;
    const int b_row = l7 + ((lane & 16) ? 8 : 0);
    const int b_kc8 = (lane & 8) ? 1 : 0;
    const int v_row = l7 + ((lane & 8) ? 8 : 0);
    const int v_dc8 = (lane & 16) ? 1 : 0;

    const uint32_t q_u = sm_u;
    const uint32_t k_u = sm_u + 32768;
    const uint32_t v_u = sm_u + 65536;

    stage(blockIdx.x); CP_COMMIT();

    for (int tile = blockIdx.x; tile < AT_NTILES; tile += AT_GRID) {
        CP_WAIT0();
        __syncthreads();

        const int h = tile & 7;
        const size_t rowbase = (size_t)(tile >> 3) * 128;

        // ---- rope in place on Q and K ----
        #pragma unroll
        for (int it = 0; it < 16; it++) {
            const int task = tid + it * 256;
            const int i  = task >> 5;
            const int dp = task & 31;
            const int d  = dp << 1;
            const int clo = (d >> 3) ^ (i & 7);
            const int chi = ((d + 64) >> 3) ^ (i & 7);
            const int ib  = (d << 1) & 15;
            const uint32_t lo = i * 256 + (clo << 4) + ib;
            const uint32_t hi = i * 256 + (chi << 4) + ib;
            const float2 sc_lo = rope[i * 64 + dp];
            const float2 sc_hi = rope[i * 64 + dp + 32];
            {
                half2* plo = (half2*)(sha + lo);
                half2* phi = (half2*)(sha + hi);
                float2 a = __half22float2(*plo);
                float2 b = __half22float2(*phi);
                *plo = __floats2half2_rn(a.x * sc_lo.y - b.x * sc_lo.x,
                                         a.y * sc_lo.y - b.y * sc_lo.x);
                *phi = __floats2half2_rn(b.x * sc_hi.y + a.x * sc_hi.x,
                                         b.y * sc_hi.y + a.y * sc_hi.x);
            }
            {
                half2* plo = (half2*)(sha + 32768 + lo);
                half2* phi = (half2*)(sha + 32768 + hi);
                float2 a = __half22float2(*plo);
                float2 b = __half22float2(*phi);
                *plo = __floats2half2_rn(a.x * sc_lo.y - b.x * sc_lo.x,
                                         a.y * sc_lo.y - b.y * sc_lo.x);
                *phi = __floats2half2_rn(b.x * sc_hi.y + a.x * sc_hi.x,
                                         b.y * sc_hi.y + a.y * sc_hi.x);
            }
        }
        __syncthreads();

        // ---- scores: S = Q K^T ----
        float acc[16][4];
        #pragma unroll
        for (int nt = 0; nt < 16; nt++)
            #pragma unroll
            for (int i = 0; i < 4; i++) acc[nt][i] = 0.f;

        #pragma unroll
        for (int kc = 0; kc < 8; kc++) {
            uint32_t a0, a1, a2, a3;
            const int ca = (kc * 2 + a_kc8) ^ (a_row & 7);
            ldsm_x4(a0, a1, a2, a3, q_u + a_row * 256 + (ca << 4));
            #pragma unroll
            for (int np = 0; np < 8; np++) {
                const int row = np * 16 + b_row;
                const int cb = (kc * 2 + b_kc8) ^ (row & 7);
                uint32_t b0, b1, c0, c1;
                ldsm_x4(b0, b1, c0, c1, k_u + row * 256 + (cb << 4));
                mma16(acc[2 * np],     a0, a1, a2, a3, b0, b1);
                mma16(acc[2 * np + 1], a0, a1, a2, a3, c0, c1);
            }
        }

        // ---- softmax ----
        const float scl = 0.08838834764831845f;
        float mx0 = -1e30f, mx1 = -1e30f;
        #pragma unroll
        for (int nt = 0; nt < 16; nt++) {
            acc[nt][0] *= scl; acc[nt][1] *= scl;
            acc[nt][2] *= scl; acc[nt][3] *= scl;
            mx0 = fmaxf(mx0, fmaxf(acc[nt][0], acc[nt][1]));
            mx1 = fmaxf(mx1, fmaxf(acc[nt][2], acc[nt][3]));
        }
        mx0 = fmaxf(mx0, __shfl_xor_sync(0xffffffffu, mx0, 1));
        mx0 = fmaxf(mx0, __shfl_xor_sync(0xffffffffu, mx0, 2));
        mx1 = fmaxf(mx1, __shfl_xor_sync(0xffffffffu, mx1, 1));
        mx1 = fmaxf(mx1, __shfl_xor_sync(0xffffffffu, mx1, 2));

        float s0 = 0.f, s1 = 0.f;
        #pragma unroll
        for (int nt = 0; nt < 16; nt++) {
            acc[nt][0] = __expf(acc[nt][0] - mx0);
            acc[nt][1] = __expf(acc[nt][1] - mx0);
            acc[nt][2] = __expf(acc[nt][2] - mx1);
            acc[nt][3] = __expf(acc[nt][3] - mx1);
            s0 += acc[nt][0] + acc[nt][1];
            s1 += acc[nt][2] + acc[nt][3];
        }
        s0 += __shfl_xor_sync(0xffffffffu, s0, 1);
        s0 += __shfl_xor_sync(0xffffffffu, s0, 2);
        s1 += __shfl_xor_sync(0xffffffffu, s1, 1);
        s1 += __shfl_xor_sync(0xffffffffu, s1, 2);
        const float i0 = 1.f / s0, i1 = 1.f / s1;

        // ---- pack P into 32 regs ----
        uint32_t p[32];
        #pragma unroll
        for (int kc = 0; kc < 8; kc++) {
            p[4 * kc + 0] = h2u(__floats2half2_rn(acc[2 * kc][0] * i0, acc[2 * kc][1] * i0));
            p[4 * kc + 1] = h2u(__floats2half2_rn(acc[2 * kc][2] * i1, acc[2 * kc][3] * i1));
            p[4 * kc + 2] = h2u(__floats2half2_rn(acc[2 * kc + 1][0] * i0, acc[2 * kc + 1][1] * i0));
            p[4 * kc + 3] = h2u(__floats2half2_rn(acc[2 * kc + 1][2] * i1, acc[2 * kc + 1][3] * i1));
        }

        // ---- O = P V ----
        float o[16][4];
        #pragma unroll
        for (int nt = 0; nt < 16; nt++)
            #pragma unroll
            for (int i = 0; i < 4; i++) o[nt][i] = 0.f;

        #pragma unroll
        for (int kc = 0; kc < 8; kc++) {
            #pragma unroll
            for (int dp = 0; dp < 8; dp++) {
                const int row = kc * 16 + v_row;
                const int cv = (dp * 2 + v_dc8) ^ (row & 7);
                uint32_t b0, b1, c0, c1;
                ldsm_x4t(b0, b1, c0, c1, v_u + row * 256 + (cv << 4));
                mma16(o[2 * dp],     p[4 * kc], p[4 * kc + 1], p[4 * kc + 2], p[4 * kc + 3], b0, b1);
                mma16(o[2 * dp + 1], p[4 * kc], p[4 * kc + 1], p[4 * kc + 2], p[4 * kc + 3], c0, c1);
            }
        }

        // ---- start next tile's fill, then store O ----
        __syncthreads();
        if (tile + AT_GRID < AT_NTILES) stage(tile + AT_GRID);
        CP_COMMIT();

        const int gq = lane >> 2;
        #pragma unroll
        for (int nt = 0; nt < 16; nt++) {
            const int col = h * 128 + nt * 8 + (tig << 1);
            const int pc = perm64c(col);
            *(half2*)(obuf + (rowbase + m0 + gq) * 1024 + pc) =
                __floats2half2_rn(o[nt][0], o[nt][1]);
            *(half2*)(obuf + (rowbase + m0 + gq + 8) * 1024 + pc) =
                __floats2half2_rn(o[nt][2], o[nt][3]);
        }
    }
}

// ---------------------------------------------------------------------------
// host launcher — 8 launches; attention is #4 (profiled by ncu)
// ---------------------------------------------------------------------------
extern "C" void kernel_launch(void* const* d_in, const int* in_sizes, int n_in,
                              void* d_out, int out_size)
{
    const float* group_x = (const float*)d_in[0];
    const float* context = (const float*)d_in[1];
    const float* W_ada   = (const float*)d_in[2];
    const float* b_ada   = (const float*)d_in[3];
    const float* scale1  = (const float*)d_in[4];
    const float* W_qkv   = (const float*)d_in[5];
    const float* b_qkv   = (const float*)d_in[6];
    const float* W_out   = (const float*)d_in[7];
    const float* b_out   = (const float*)d_in[8];
    const float* scale2  = (const float*)d_in[9];
    const float* W_ff1   = (const float*)d_in[10];
    const float* b_ff1   = (const float*)d_in[11];
    const float* W_ff2   = (const float*)d_in[12];
    const float* b_ff2   = (const float*)d_in[13];
    float* out = (float*)d_out;

    float *ada, *res2;
    __half *x1, *qkv, *obuf, *hbuf, *h1, *wqkv, *wout, *wff1, *wff2;
    float2* rope;
    cudaGetSymbolAddress((void**)&ada,  g_ada);
    cudaGetSymbolAddress((void**)&x1,   g_x1);
    cudaGetSymbolAddress((void**)&qkv,  g_qkv);
    cudaGetSymbolAddress((void**)&obuf, g_o);
    cudaGetSymbolAddress((void**)&res2, g_res);
    cudaGetSymbolAddress((void**)&hbuf, g_h);
    cudaGetSymbolAddress((void**)&h1,   g_h1);
    cudaGetSymbolAddress((void**)&rope, g_rope);
    cudaGetSymbolAddress((void**)&wqkv, g_wqkv);
    cudaGetSymbolAddress((void**)&wout, g_wout);
    cudaGetSymbolAddress((void**)&wff1, g_wff1);
    cudaGetSymbolAddress((void**)&wff2, g_wff2);

    cudaFuncSetAttribute(gemm_fp16<1>, cudaFuncAttributeMaxDynamicSharedMemorySize, GEMM_SMEM);
    cudaFuncSetAttribute(gemm_fp16<2>, cudaFuncAttributeMaxDynamicSharedMemorySize, GEMM_SMEM);
    cudaFuncSetAttribute(gemm_fp16<3>, cudaFuncAttributeMaxDynamicSharedMemorySize, GEMM_SMEM);
    cudaFuncSetAttribute(attn_kernel,  cudaFuncAttributeMaxDynamicSharedMemorySize, ATTN_SMEM_BYTES);

    // 1: ada + rope + W_qkv transpose
    prep_kernel<<<3128, 256>>>(context, W_ada, b_ada, ada, rope, W_qkv, wqkv);

    // 2: norm1 (+ wout/wff1/wff2 transposes in extra blocks)
    norm_mod<<<32768 + 9216, 256>>>(group_x, scale1, ada, 0, 1024, x1,
                                    W_out, wout, W_ff1, wff1, W_ff2, wff2);

    // 3: qkv = x1 @ W_qkv + b_qkv -> fp16 natural   (N=3072, K=1024)
    gemm_fp16<3><<<dim3(12, 256), 256, GEMM_SMEM>>>(x1, wqkv, b_qkv, nullptr, qkv,
                                                    3072, 1024, nullptr, nullptr);

    // 4 (profiled): persistent attention
    attn_kernel<<<AT_GRID, 256, ATTN_SMEM_BYTES>>>(qkv, obuf, rope);

    // 5: res2 = group_x + g_msa * (obuf @ W_out + b_out)   (N=1024, K=1024)
    gemm_fp16<2><<<dim3(4, 256), 256, GEMM_SMEM>>>(obuf, wout, b_out, res2, nullptr,
                                                   1024, 1024, group_x, ada + 2048);

    // 6: norm2 (no extra blocks)
    norm_mod<<<32768, 256>>>(res2, scale2, ada, 3072, 4096, hbuf,
                             nullptr, nullptr, nullptr, nullptr, nullptr, nullptr);

    // 7: h1 = gelu(hbuf @ W_ff1 + b_ff1) -> fp16 perm64  (N=4096, K=1024)
    gemm_fp16<1><<<dim3(16, 256), 256, GEMM_SMEM>>>(hbuf, wff1, b_ff1, nullptr, h1,
                                                    4096, 1024, nullptr, nullptr);
    // 8: out = res2 + g_mlp * (h1 @ W_ff2 + b_ff2)        (N=1024, K=4096)
    gemm_fp16<2><<<dim3(4, 256), 256, GEMM_SMEM>>>(h1, wff2, b_ff2, out, nullptr,
                                                   1024, 4096, res2, ada + 5120);
}